// round 1
// baseline (speedup 1.0000x reference)
#include <cuda_runtime.h>
#include <math.h>

#define NN 50000
#define EE 300000
#define ET (EE + NN)
#define CC 256

// ---------------- scratch (device globals: no allocation allowed) ----------
__device__ float g_h[NN * CC];     // per-layer transformed features
__device__ float g_acc1[NN * CC];  // layer-1 aggregation output
__device__ float g_acc2[NN * CC];  // layer-2 aggregation output
__device__ float g_as[NN];
__device__ float g_ad[NN];
__device__ float g_m[NN];
__device__ float g_den[NN];
__device__ float g_e[ET];
__device__ float g_Wt[CC * CC];

// ---------------- helpers ----------------
__device__ __forceinline__ void atomicMaxF(float* addr, float v) {
    if (v >= 0.0f) {
        atomicMax((int*)addr, __float_as_int(v));
    } else {
        atomicMin((unsigned int*)addr, __float_as_uint(v));
    }
}

__device__ __forceinline__ void redAddV4(float4* addr, float4 v) {
    asm volatile("red.global.add.v4.f32 [%0], {%1, %2, %3, %4};"
                 :: "l"(addr), "f"(v.x), "f"(v.y), "f"(v.z), "f"(v.w)
                 : "memory");
}

// ---------------- init: zero acc buffer + node scalars ----------------
__global__ void init_kernel(float* __restrict__ acc) {
    int tid = blockIdx.x * blockDim.x + threadIdx.x;
    int stride = gridDim.x * blockDim.x;
    float4 z = make_float4(0.f, 0.f, 0.f, 0.f);
    float4* acc4 = (float4*)acc;
    const int n4 = NN * CC / 4;
    for (int i = tid; i < n4; i += stride) acc4[i] = z;
    for (int i = tid; i < NN; i += stride) {
        g_m[i] = -INFINITY;
        g_den[i] = 0.f;
    }
}

// ---------------- SGEMM: C[M,256] = A[M,256] @ B[256,256] (+bias)(+relu) ---
// 128x128 block tile, 8x8 per thread, K-tile 8, 256 threads.
__global__ __launch_bounds__(256)
void sgemm_kernel(const float* __restrict__ A, const float* __restrict__ B,
                  float* __restrict__ C, const float* __restrict__ bias,
                  int M, int relu) {
    const int K = CC, Nc = CC;
    __shared__ float As[8][128];
    __shared__ float Bs[8][128];

    int tid = threadIdx.x;
    int tx = tid & 15;        // 0..15 -> 8 columns each
    int ty = tid >> 4;        // 0..15 -> 8 rows each
    int rowBase = blockIdx.y * 128;
    int colBase = blockIdx.x * 128;

    // A load mapping: one float4 per thread
    int aRow  = tid >> 1;          // 0..127
    int aCol4 = (tid & 1) * 4;     // 0 or 4
    // B load mapping: one float4 per thread
    int bRow  = tid >> 5;          // 0..7
    int bCol4 = (tid & 31) * 4;    // 0..124

    float acc[8][8];
#pragma unroll
    for (int i = 0; i < 8; i++)
#pragma unroll
        for (int j = 0; j < 8; j++) acc[i][j] = 0.f;

    for (int kt = 0; kt < K; kt += 8) {
        float4 av;
        int gr = rowBase + aRow;
        if (gr < M) av = *(const float4*)(A + (size_t)gr * K + kt + aCol4);
        else        av = make_float4(0.f, 0.f, 0.f, 0.f);
        As[aCol4 + 0][aRow] = av.x;
        As[aCol4 + 1][aRow] = av.y;
        As[aCol4 + 2][aRow] = av.z;
        As[aCol4 + 3][aRow] = av.w;

        float4 bv = *(const float4*)(B + (size_t)(kt + bRow) * Nc + colBase + bCol4);
        *(float4*)&Bs[bRow][bCol4] = bv;

        __syncthreads();

#pragma unroll
        for (int k = 0; k < 8; k++) {
            float a[8], b[8];
            float4 a0 = *(const float4*)&As[k][ty * 8];
            float4 a1 = *(const float4*)&As[k][ty * 8 + 4];
            float4 b0 = *(const float4*)&Bs[k][tx * 8];
            float4 b1 = *(const float4*)&Bs[k][tx * 8 + 4];
            a[0]=a0.x; a[1]=a0.y; a[2]=a0.z; a[3]=a0.w;
            a[4]=a1.x; a[5]=a1.y; a[6]=a1.z; a[7]=a1.w;
            b[0]=b0.x; b[1]=b0.y; b[2]=b0.z; b[3]=b0.w;
            b[4]=b1.x; b[5]=b1.y; b[6]=b1.z; b[7]=b1.w;
#pragma unroll
            for (int i = 0; i < 8; i++)
#pragma unroll
                for (int j = 0; j < 8; j++)
                    acc[i][j] = fmaf(a[i], b[j], acc[i][j]);
        }
        __syncthreads();
    }

#pragma unroll
    for (int i = 0; i < 8; i++) {
        int gr = rowBase + ty * 8 + i;
        if (gr >= M) continue;
#pragma unroll
        for (int j = 0; j < 8; j += 4) {
            int gc = colBase + tx * 8 + j;
            float4 v = make_float4(acc[i][j], acc[i][j+1], acc[i][j+2], acc[i][j+3]);
            if (bias) {
                v.x += bias[gc + 0]; v.y += bias[gc + 1];
                v.z += bias[gc + 2]; v.w += bias[gc + 3];
            }
            if (relu) {
                v.x = fmaxf(v.x, 0.f); v.y = fmaxf(v.y, 0.f);
                v.z = fmaxf(v.z, 0.f); v.w = fmaxf(v.w, 0.f);
            }
            *(float4*)(C + (size_t)gr * Nc + gc) = v;
        }
    }
}

// ---------------- alpha_src / alpha_dst: one warp per node ----------------
__global__ void alphas_kernel(const float* __restrict__ h,
                              const float* __restrict__ a_src,
                              const float* __restrict__ a_dst) {
    int warp = (blockIdx.x * blockDim.x + threadIdx.x) >> 5;
    int lane = threadIdx.x & 31;
    if (warp >= NN) return;
    const float* row = h + (size_t)warp * CC;
    float s = 0.f, d = 0.f;
#pragma unroll
    for (int k = 0; k < 8; k++) {
        float v = row[lane + k * 32];
        s = fmaf(v, a_src[lane + k * 32], s);
        d = fmaf(v, a_dst[lane + k * 32], d);
    }
#pragma unroll
    for (int off = 16; off > 0; off >>= 1) {
        s += __shfl_xor_sync(0xffffffff, s, off);
        d += __shfl_xor_sync(0xffffffff, d, off);
    }
    if (lane == 0) {
        g_as[warp] = s;
        g_ad[warp] = d;
    }
}

// ---------------- edge max: e = leaky_relu(as[src]+ad[dst]); m[dst]=max ----
__global__ void edge_max_kernel(const int* __restrict__ src,
                                const int* __restrict__ dst) {
    int i = blockIdx.x * blockDim.x + threadIdx.x;
    if (i >= ET) return;
    int s, d;
    if (i < EE) { s = src[i]; d = dst[i]; }
    else        { s = d = i - EE; }
    float e = g_as[s] + g_ad[d];
    e = (e > 0.f) ? e : 0.2f * e;
    g_e[i] = e;
    atomicMaxF(&g_m[d], e);
}

// ---------------- edge exp: ex = exp(e - m[dst]); den[dst] += ex ----------
__global__ void edge_exp_kernel(const int* __restrict__ src,
                                const int* __restrict__ dst) {
    int i = blockIdx.x * blockDim.x + threadIdx.x;
    if (i >= ET) return;
    int d = (i < EE) ? dst[i] : (i - EE);
    float ex = expf(g_e[i] - g_m[d]);
    g_e[i] = ex;
    atomicAdd(&g_den[d], ex);
}

// ---------------- edge aggregate: out[dst] += h[src] * (ex/den[dst]) ------
// one warp per edge, float4 vector reductions
__global__ __launch_bounds__(256)
void edge_aggr_kernel(const int* __restrict__ src,
                      const int* __restrict__ dst,
                      const float* __restrict__ h,
                      float* __restrict__ out) {
    int warp = (blockIdx.x * blockDim.x + threadIdx.x) >> 5;
    int lane = threadIdx.x & 31;
    if (warp >= ET) return;
    int s, d;
    if (warp < EE) { s = src[warp]; d = dst[warp]; }
    else           { s = d = warp - EE; }
    float w = g_e[warp] / g_den[d];
    const float4* hp = (const float4*)(h + (size_t)s * CC);
    float4* op = (float4*)(out + (size_t)d * CC);
#pragma unroll
    for (int j = 0; j < 2; j++) {
        float4 v = __ldg(hp + lane + j * 32);
        v.x *= w; v.y *= w; v.z *= w; v.w *= w;
        redAddV4(op + lane + j * 32, v);
    }
}

// ---------------- bias + relu (in place) ----------------
__global__ void bias_relu_kernel(float* __restrict__ x,
                                 const float* __restrict__ bias) {
    int tid = blockIdx.x * blockDim.x + threadIdx.x;
    int stride = gridDim.x * blockDim.x;
    float4* x4 = (float4*)x;
    const int n4 = NN * CC / 4;
    for (int i = tid; i < n4; i += stride) {
        int col4 = (i & 63) * 4;
        float4 v = x4[i];
        v.x = fmaxf(v.x + bias[col4 + 0], 0.f);
        v.y = fmaxf(v.y + bias[col4 + 1], 0.f);
        v.z = fmaxf(v.z + bias[col4 + 2], 0.f);
        v.w = fmaxf(v.w + bias[col4 + 3], 0.f);
        x4[i] = v;
    }
}

// ---------------- transpose Wl (torch [out,in] -> [in,out]) ---------------
__global__ void transpose_kernel(const float* __restrict__ W) {
    int j = blockIdx.x;   // output-feature index (row of Wl)
    int k = threadIdx.x;  // input-feature index
    g_Wt[k * CC + j] = W[j * CC + k];
}

// ---------------- launch ----------------
extern "C" void kernel_launch(void* const* d_in, const int* in_sizes, int n_in,
                              void* d_out, int out_size) {
    const float* x    = (const float*)d_in[0];
    const int*   ei   = (const int*)d_in[1];
    const float* W1   = (const float*)d_in[2];
    const float* a1s  = (const float*)d_in[3];
    const float* a1d  = (const float*)d_in[4];
    const float* b1   = (const float*)d_in[5];
    const float* W2   = (const float*)d_in[6];
    const float* a2s  = (const float*)d_in[7];
    const float* a2d  = (const float*)d_in[8];
    const float* b2   = (const float*)d_in[9];
    const float* Wl   = (const float*)d_in[10];
    const float* bl   = (const float*)d_in[11];
    float* out = (float*)d_out;

    const int* src = ei;
    const int* dst = ei + EE;

    float *ph, *pacc1, *pacc2, *pWt;
    cudaGetSymbolAddress((void**)&ph,    g_h);
    cudaGetSymbolAddress((void**)&pacc1, g_acc1);
    cudaGetSymbolAddress((void**)&pacc2, g_acc2);
    cudaGetSymbolAddress((void**)&pWt,   g_Wt);

    dim3 gemmGrid(2, (NN + 127) / 128);
    int edgeBlocks = (ET + 255) / 256;
    int aggrBlocks = (ET * 32 + 255) / 256;
    int alphaBlocks = (NN + 7) / 8;  // 8 warps per block

    // ---- layer 1 ----
    init_kernel<<<2048, 256>>>(pacc1);
    sgemm_kernel<<<gemmGrid, 256>>>(x, W1, ph, nullptr, NN, 0);
    alphas_kernel<<<alphaBlocks, 256>>>(ph, a1s, a1d);
    edge_max_kernel<<<edgeBlocks, 256>>>(src, dst);
    edge_exp_kernel<<<edgeBlocks, 256>>>(src, dst);
    edge_aggr_kernel<<<aggrBlocks, 256>>>(src, dst, ph, pacc1);
    bias_relu_kernel<<<2048, 256>>>(pacc1, b1);

    // ---- layer 2 ----
    init_kernel<<<2048, 256>>>(pacc2);
    sgemm_kernel<<<gemmGrid, 256>>>(pacc1, W2, ph, nullptr, NN, 0);
    alphas_kernel<<<alphaBlocks, 256>>>(ph, a2s, a2d);
    edge_max_kernel<<<edgeBlocks, 256>>>(src, dst);
    edge_exp_kernel<<<edgeBlocks, 256>>>(src, dst);
    edge_aggr_kernel<<<aggrBlocks, 256>>>(src, dst, ph, pacc2);
    bias_relu_kernel<<<2048, 256>>>(pacc2, b2);

    // ---- final linear: out = acc2 @ Wl^T + bl ----
    transpose_kernel<<<CC, CC>>>(Wl);
    sgemm_kernel<<<gemmGrid, 256>>>(pacc2, pWt, out, bl, NN, 0);
}

// round 3
// speedup vs baseline: 1.6316x; 1.6316x over previous
#include <cuda_runtime.h>
#include <cuda_bf16.h>
#include <cstdint>
#include <math.h>

#define NN 50000
#define EE 300000
#define ET (EE + NN)
#define CC 256

// ---------------- scratch (device globals) ----------------
__device__ float g_h[NN * CC];             // GEMM output (transformed features)
__device__ float g_acc[NN * CC];           // aggregation output (per layer, reused)
__device__ __nv_bfloat16 g_Ahi[NN * CC];   // GEMM A operand, hi part
__device__ __nv_bfloat16 g_Alo[NN * CC];   // GEMM A operand, lo part
__device__ __nv_bfloat16 g_Bhi[CC * CC];   // GEMM B operand [N][K], hi
__device__ __nv_bfloat16 g_Blo[CC * CC];   // GEMM B operand [N][K], lo
__device__ float g_as[NN];
__device__ float g_ad[NN];
__device__ float g_m[NN];
__device__ float g_den[NN];
__device__ float g_e[ET];

// ---------------- helpers ----------------
__device__ __forceinline__ void atomicMaxF(float* addr, float v) {
    if (v >= 0.0f) atomicMax((int*)addr, __float_as_int(v));
    else           atomicMin((unsigned int*)addr, __float_as_uint(v));
}

__device__ __forceinline__ void redAddV4(float4* addr, float4 v) {
    asm volatile("red.global.add.v4.f32 [%0], {%1, %2, %3, %4};"
                 :: "l"(addr), "f"(v.x), "f"(v.y), "f"(v.z), "f"(v.w)
                 : "memory");
}

__device__ __forceinline__ void cpasync16(void* dst_smem, const void* src, int srcsize) {
    uint32_t d = (uint32_t)__cvta_generic_to_shared(dst_smem);
    asm volatile("cp.async.cg.shared.global [%0], [%1], 16, %2;"
                 :: "r"(d), "l"(src), "r"(srcsize));
}

#define MMA_BF16(d, a, b) \
    asm volatile("mma.sync.aligned.m16n8k16.row.col.f32.bf16.bf16.f32 " \
                 "{%0,%1,%2,%3}, {%4,%5,%6,%7}, {%8,%9}, {%0,%1,%2,%3};" \
                 : "+f"(d[0]), "+f"(d[1]), "+f"(d[2]), "+f"(d[3]) \
                 : "r"(a[0]), "r"(a[1]), "r"(a[2]), "r"(a[3]), "r"(b[0]), "r"(b[1]))

// ---------------- init: zero acc buffer + node scalars ----------------
__global__ void init_kernel(float* __restrict__ acc) {
    int tid = blockIdx.x * blockDim.x + threadIdx.x;
    int stride = gridDim.x * blockDim.x;
    float4 z = make_float4(0.f, 0.f, 0.f, 0.f);
    float4* acc4 = (float4*)acc;
    const int n4 = NN * CC / 4;
    for (int i = tid; i < n4; i += stride) acc4[i] = z;
    for (int i = tid; i < NN; i += stride) {
        g_m[i] = -INFINITY;
        g_den[i] = 0.f;
    }
}

// ---------------- split fp32 -> bf16 hi/lo ----------------
__device__ __forceinline__ void split1(float v, __nv_bfloat16& h, __nv_bfloat16& l) {
    h = __float2bfloat16(v);
    l = __float2bfloat16(v - __bfloat162float(h));
}

__global__ void split_x_kernel(const float* __restrict__ X) {
    int tid = blockIdx.x * blockDim.x + threadIdx.x;
    int stride = gridDim.x * blockDim.x;
    const int n4 = NN * CC / 4;
    __nv_bfloat162* H = (__nv_bfloat162*)g_Ahi;
    __nv_bfloat162* L = (__nv_bfloat162*)g_Alo;
    for (int i = tid; i < n4; i += stride) {
        float4 v = ((const float4*)X)[i];
        __nv_bfloat16 h0,h1,h2,h3,l0,l1,l2,l3;
        split1(v.x,h0,l0); split1(v.y,h1,l1); split1(v.z,h2,l2); split1(v.w,h3,l3);
        H[2*i]   = __nv_bfloat162(h0,h1);
        H[2*i+1] = __nv_bfloat162(h2,h3);
        L[2*i]   = __nv_bfloat162(l0,l1);
        L[2*i+1] = __nv_bfloat162(l2,l3);
    }
}

// bias + relu on acc, emit bf16 hi/lo directly (acc fp32 not needed afterwards)
__global__ void bias_relu_split_kernel(const float* __restrict__ acc,
                                       const float* __restrict__ bias) {
    int tid = blockIdx.x * blockDim.x + threadIdx.x;
    int stride = gridDim.x * blockDim.x;
    const int n4 = NN * CC / 4;
    __nv_bfloat162* H = (__nv_bfloat162*)g_Ahi;
    __nv_bfloat162* L = (__nv_bfloat162*)g_Alo;
    for (int i = tid; i < n4; i += stride) {
        int col4 = (i & 63) * 4;
        float4 v = ((const float4*)acc)[i];
        v.x = fmaxf(v.x + bias[col4 + 0], 0.f);
        v.y = fmaxf(v.y + bias[col4 + 1], 0.f);
        v.z = fmaxf(v.z + bias[col4 + 2], 0.f);
        v.w = fmaxf(v.w + bias[col4 + 3], 0.f);
        __nv_bfloat16 h0,h1,h2,h3,l0,l1,l2,l3;
        split1(v.x,h0,l0); split1(v.y,h1,l1); split1(v.z,h2,l2); split1(v.w,h3,l3);
        H[2*i]   = __nv_bfloat162(h0,h1);
        H[2*i+1] = __nv_bfloat162(h2,h3);
        L[2*i]   = __nv_bfloat162(l0,l1);
        L[2*i+1] = __nv_bfloat162(l2,l3);
    }
}

// weight split: W [K,N] -> Bt [N,K] (transpose), or Wl [N,K] -> direct copy-split
__global__ void splitW_T_kernel(const float* __restrict__ W) {
    int n = blockIdx.x, k = threadIdx.x;
    float v = W[k * CC + n];
    split1(v, g_Bhi[n * CC + k], g_Blo[n * CC + k]);
}
__global__ void splitW_N_kernel(const float* __restrict__ W) {
    int n = blockIdx.x, k = threadIdx.x;
    float v = W[n * CC + k];
    split1(v, g_Bhi[n * CC + k], g_Blo[n * CC + k]);
}

// ---------------- bf16-split tensor-core GEMM ----------------
// C[M,256] = Ahi@Bhi^T + Ahi@Blo^T + Alo@Bhi^T  (B stored [N,K])
// 128x128 CTA tile, 8 warps (2M x 4N), warp tile 64x32, BK=32, 2-stage cp.async.
#define SPAD 40            // smem row stride in bf16 elems (32 + 8 pad)
#define STAGE_E (128*SPAD) // 5120 elems per matrix per stage

__global__ __launch_bounds__(256, 2)
void gemm_bf16split(const __nv_bfloat16* __restrict__ Ah,
                    const __nv_bfloat16* __restrict__ Al,
                    const __nv_bfloat16* __restrict__ Bh,
                    const __nv_bfloat16* __restrict__ Bl,
                    float* __restrict__ C,
                    const float* __restrict__ bias,
                    int M, int relu) {
    extern __shared__ __nv_bfloat16 sm[];
    __nv_bfloat16* sAh = sm;
    __nv_bfloat16* sAl = sm + 2 * STAGE_E;
    __nv_bfloat16* sBh = sm + 4 * STAGE_E;
    __nv_bfloat16* sBl = sm + 6 * STAGE_E;

    const int tid = threadIdx.x;
    const int lane = tid & 31;
    const int wid = tid >> 5;
    const int warpM = wid & 1;       // 0..1, 64 rows each
    const int warpN = wid >> 1;      // 0..3, 32 cols each
    const int g = lane >> 2;
    const int t = lane & 3;
    const int M0 = blockIdx.y * 128;
    const int colBase = blockIdx.x * 128;

    // loader mapping: 512 16B-chunks per (matrix, stage); 2 per thread
    const int row0 = tid >> 2;             // chunk set 0: rows 0..63
    const int cc0  = tid & 3;
    const int row1 = (tid + 256) >> 2;     // chunk set 1: rows 64..127

    float acc[4][4][4];
#pragma unroll
    for (int i = 0; i < 4; i++)
#pragma unroll
        for (int j = 0; j < 4; j++)
#pragma unroll
            for (int k = 0; k < 4; k++) acc[i][j][k] = 0.f;

    auto loadTiles = [&](int stage, int kt) {
        __nv_bfloat16* dAh = sAh + stage * STAGE_E;
        __nv_bfloat16* dAl = sAl + stage * STAGE_E;
        __nv_bfloat16* dBh = sBh + stage * STAGE_E;
        __nv_bfloat16* dBl = sBl + stage * STAGE_E;
        // A rows (guarded against M)
        {
            int gr = M0 + row0;
            int sz = (gr < M) ? 16 : 0;
            int gro = (gr < M) ? gr : 0;
            size_t go = (size_t)gro * CC + kt + cc0 * 8;
            cpasync16(dAh + row0 * SPAD + cc0 * 8, Ah + go, sz);
            cpasync16(dAl + row0 * SPAD + cc0 * 8, Al + go, sz);
        }
        {
            int gr = M0 + row1;
            int sz = (gr < M) ? 16 : 0;
            int gro = (gr < M) ? gr : 0;
            size_t go = (size_t)gro * CC + kt + cc0 * 8;
            cpasync16(dAh + row1 * SPAD + cc0 * 8, Ah + go, sz);
            cpasync16(dAl + row1 * SPAD + cc0 * 8, Al + go, sz);
        }
        // B rows (N=256, always valid)
        {
            size_t go = (size_t)(colBase + row0) * CC + kt + cc0 * 8;
            cpasync16(dBh + row0 * SPAD + cc0 * 8, Bh + go, 16);
            cpasync16(dBl + row0 * SPAD + cc0 * 8, Bl + go, 16);
            size_t go1 = (size_t)(colBase + row1) * CC + kt + cc0 * 8;
            cpasync16(dBh + row1 * SPAD + cc0 * 8, Bh + go1, 16);
            cpasync16(dBl + row1 * SPAD + cc0 * 8, Bl + go1, 16);
        }
    };

    loadTiles(0, 0);
    asm volatile("cp.async.commit_group;");

    const int arow = warpM * 64 + g;
    const int n0 = warpN * 32 + g;

    for (int kt = 0; kt < 8; kt++) {
        if (kt < 7) {
            loadTiles((kt + 1) & 1, (kt + 1) * 32);
            asm volatile("cp.async.commit_group;");
            asm volatile("cp.async.wait_group 1;");
        } else {
            asm volatile("cp.async.wait_group 0;");
        }
        __syncthreads();

        int stage = kt & 1;
        const __nv_bfloat16* bAh = sAh + stage * STAGE_E;
        const __nv_bfloat16* bAl = sAl + stage * STAGE_E;
        const __nv_bfloat16* bBh = sBh + stage * STAGE_E;
        const __nv_bfloat16* bBl = sBl + stage * STAGE_E;

#pragma unroll
        for (int ks = 0; ks < 32; ks += 16) {
            uint32_t af[4][4], bhf[4][2], blf[4][2];
            const uint32_t* pa = (const uint32_t*)(bAh + arow * SPAD + ks + 2 * t);
#pragma unroll
            for (int mt = 0; mt < 4; mt++) {
                af[mt][0] = pa[mt * 320];
                af[mt][1] = pa[mt * 320 + 160];
                af[mt][2] = pa[mt * 320 + 4];
                af[mt][3] = pa[mt * 320 + 164];
            }
            const uint32_t* pbh = (const uint32_t*)(bBh + n0 * SPAD + ks + 2 * t);
            const uint32_t* pbl = (const uint32_t*)(bBl + n0 * SPAD + ks + 2 * t);
#pragma unroll
            for (int nt = 0; nt < 4; nt++) {
                bhf[nt][0] = pbh[nt * 160];
                bhf[nt][1] = pbh[nt * 160 + 4];
                blf[nt][0] = pbl[nt * 160];
                blf[nt][1] = pbl[nt * 160 + 4];
            }
            // pass 1: Ahi * Bhi
#pragma unroll
            for (int mt = 0; mt < 4; mt++)
#pragma unroll
                for (int nt = 0; nt < 4; nt++)
                    MMA_BF16(acc[mt][nt], af[mt], bhf[nt]);
            // pass 2: Ahi * Blo
#pragma unroll
            for (int mt = 0; mt < 4; mt++)
#pragma unroll
                for (int nt = 0; nt < 4; nt++)
                    MMA_BF16(acc[mt][nt], af[mt], blf[nt]);
            // pass 3: Alo * Bhi (reload A frags from lo buffer)
            const uint32_t* pal = (const uint32_t*)(bAl + arow * SPAD + ks + 2 * t);
#pragma unroll
            for (int mt = 0; mt < 4; mt++) {
                af[mt][0] = pal[mt * 320];
                af[mt][1] = pal[mt * 320 + 160];
                af[mt][2] = pal[mt * 320 + 4];
                af[mt][3] = pal[mt * 320 + 164];
            }
#pragma unroll
            for (int mt = 0; mt < 4; mt++)
#pragma unroll
                for (int nt = 0; nt < 4; nt++)
                    MMA_BF16(acc[mt][nt], af[mt], bhf[nt]);
        }
        __syncthreads();
    }

    // epilogue
#pragma unroll
    for (int mt = 0; mt < 4; mt++) {
        int r0 = M0 + warpM * 64 + mt * 16 + g;
#pragma unroll
        for (int nt = 0; nt < 4; nt++) {
            int c0 = colBase + warpN * 32 + nt * 8 + 2 * t;
            float2 v01 = make_float2(acc[mt][nt][0], acc[mt][nt][1]);
            float2 v23 = make_float2(acc[mt][nt][2], acc[mt][nt][3]);
            if (bias) {
                float b0 = bias[c0], b1 = bias[c0 + 1];
                v01.x += b0; v01.y += b1;
                v23.x += b0; v23.y += b1;
            }
            if (relu) {
                v01.x = fmaxf(v01.x, 0.f); v01.y = fmaxf(v01.y, 0.f);
                v23.x = fmaxf(v23.x, 0.f); v23.y = fmaxf(v23.y, 0.f);
            }
            if (r0 < M)     *(float2*)(C + (size_t)r0 * CC + c0) = v01;
            if (r0 + 8 < M) *(float2*)(C + (size_t)(r0 + 8) * CC + c0) = v23;
        }
    }
}

// ---------------- alpha_src / alpha_dst: one warp per node ----------------
__global__ void alphas_kernel(const float* __restrict__ h,
                              const float* __restrict__ a_src,
                              const float* __restrict__ a_dst) {
    int warp = (blockIdx.x * blockDim.x + threadIdx.x) >> 5;
    int lane = threadIdx.x & 31;
    if (warp >= NN) return;
    const float* row = h + (size_t)warp * CC;
    float s = 0.f, d = 0.f;
#pragma unroll
    for (int k = 0; k < 8; k++) {
        float v = row[lane + k * 32];
        s = fmaf(v, a_src[lane + k * 32], s);
        d = fmaf(v, a_dst[lane + k * 32], d);
    }
#pragma unroll
    for (int off = 16; off > 0; off >>= 1) {
        s += __shfl_xor_sync(0xffffffff, s, off);
        d += __shfl_xor_sync(0xffffffff, d, off);
    }
    if (lane == 0) {
        g_as[warp] = s;
        g_ad[warp] = d;
    }
}

// ---------------- edge max ----------------
__global__ void edge_max_kernel(const int* __restrict__ src,
                                const int* __restrict__ dst) {
    int i = blockIdx.x * blockDim.x + threadIdx.x;
    if (i >= ET) return;
    int s, d;
    if (i < EE) { s = src[i]; d = dst[i]; }
    else        { s = d = i - EE; }
    float e = g_as[s] + g_ad[d];
    e = (e > 0.f) ? e : 0.2f * e;
    g_e[i] = e;
    atomicMaxF(&g_m[d], e);
}

// ---------------- edge exp ----------------
__global__ void edge_exp_kernel(const int* __restrict__ src,
                                const int* __restrict__ dst) {
    int i = blockIdx.x * blockDim.x + threadIdx.x;
    if (i >= ET) return;
    int d = (i < EE) ? dst[i] : (i - EE);
    float ex = expf(g_e[i] - g_m[d]);
    g_e[i] = ex;
    atomicAdd(&g_den[d], ex);
}

// ---------------- edge aggregate: out[dst] += h[src] * (ex/den[dst]) ------
__global__ __launch_bounds__(256)
void edge_aggr_kernel(const int* __restrict__ src,
                      const int* __restrict__ dst,
                      const float* __restrict__ h,
                      float* __restrict__ out) {
    int warp = (blockIdx.x * blockDim.x + threadIdx.x) >> 5;
    int lane = threadIdx.x & 31;
    if (warp >= ET) return;
    int s, d;
    if (warp < EE) { s = src[warp]; d = dst[warp]; }
    else           { s = d = warp - EE; }
    float w = g_e[warp] / g_den[d];
    const float4* hp = (const float4*)(h + (size_t)s * CC);
    float4* op = (float4*)(out + (size_t)d * CC);
#pragma unroll
    for (int j = 0; j < 2; j++) {
        float4 v = __ldg(hp + lane + j * 32);
        v.x *= w; v.y *= w; v.z *= w; v.w *= w;
        redAddV4(op + lane + j * 32, v);
    }
}

// ---------------- launch ----------------
extern "C" void kernel_launch(void* const* d_in, const int* in_sizes, int n_in,
                              void* d_out, int out_size) {
    const float* x    = (const float*)d_in[0];
    const int*   ei   = (const int*)d_in[1];
    const float* W1   = (const float*)d_in[2];
    const float* a1s  = (const float*)d_in[3];
    const float* a1d  = (const float*)d_in[4];
    const float* b1   = (const float*)d_in[5];
    const float* W2   = (const float*)d_in[6];
    const float* a2s  = (const float*)d_in[7];
    const float* a2d  = (const float*)d_in[8];
    const float* b2   = (const float*)d_in[9];
    const float* Wl   = (const float*)d_in[10];
    const float* bl   = (const float*)d_in[11];
    float* out = (float*)d_out;

    const int* src = ei;
    const int* dst = ei + EE;

    float *ph, *pacc;
    __nv_bfloat16 *pAh, *pAl, *pBh, *pBl;
    cudaGetSymbolAddress((void**)&ph,   g_h);
    cudaGetSymbolAddress((void**)&pacc, g_acc);
    cudaGetSymbolAddress((void**)&pAh,  g_Ahi);
    cudaGetSymbolAddress((void**)&pAl,  g_Alo);
    cudaGetSymbolAddress((void**)&pBh,  g_Bhi);
    cudaGetSymbolAddress((void**)&pBl,  g_Blo);

    static const int SMEM_BYTES = 8 * STAGE_E * 2;  // 81920
    cudaFuncSetAttribute(gemm_bf16split,
                         cudaFuncAttributeMaxDynamicSharedMemorySize, SMEM_BYTES);

    dim3 gemmGrid(2, (NN + 127) / 128);
    int edgeBlocks = (ET + 255) / 256;
    int aggrBlocks = (ET * 32 + 255) / 256;
    int alphaBlocks = (NN + 7) / 8;

    // ---- layer 1 ----
    split_x_kernel<<<2048, 256>>>(x);
    splitW_T_kernel<<<CC, CC>>>(W1);
    gemm_bf16split<<<gemmGrid, 256, SMEM_BYTES>>>(pAh, pAl, pBh, pBl, ph, nullptr, NN, 0);
    init_kernel<<<2048, 256>>>(pacc);
    alphas_kernel<<<alphaBlocks, 256>>>(ph, a1s, a1d);
    edge_max_kernel<<<edgeBlocks, 256>>>(src, dst);
    edge_exp_kernel<<<edgeBlocks, 256>>>(src, dst);
    edge_aggr_kernel<<<aggrBlocks, 256>>>(src, dst, ph, pacc);
    bias_relu_split_kernel<<<2048, 256>>>(pacc, b1);

    // ---- layer 2 ----
    splitW_T_kernel<<<CC, CC>>>(W2);
    gemm_bf16split<<<gemmGrid, 256, SMEM_BYTES>>>(pAh, pAl, pBh, pBl, ph, nullptr, NN, 0);
    init_kernel<<<2048, 256>>>(pacc);
    alphas_kernel<<<alphaBlocks, 256>>>(ph, a2s, a2d);
    edge_max_kernel<<<edgeBlocks, 256>>>(src, dst);
    edge_exp_kernel<<<edgeBlocks, 256>>>(src, dst);
    edge_aggr_kernel<<<aggrBlocks, 256>>>(src, dst, ph, pacc);
    bias_relu_split_kernel<<<2048, 256>>>(pacc, b2);

    // ---- final linear: out = acc @ Wl^T + bl ----
    splitW_N_kernel<<<CC, CC>>>(Wl);
    gemm_bf16split<<<gemmGrid, 256, SMEM_BYTES>>>(pAh, pAl, pBh, pBl, out, bl, NN, 0);
}

// round 4
// speedup vs baseline: 1.7880x; 1.0959x over previous
#include <cuda_runtime.h>
#include <cuda_bf16.h>
#include <cstdint>
#include <math.h>

#define NN 50000
#define EE 300000
#define ET (EE + NN)
#define CC 256

// ---------------- scratch (device globals) ----------------
__device__ float g_h[NN * CC];             // GEMM output (transformed features)
__device__ float g_acc[NN * CC];           // aggregation output (per layer, reused)
__device__ __nv_bfloat16 g_Ahi[NN * CC];   // GEMM A operand, hi part
__device__ __nv_bfloat16 g_Alo[NN * CC];   // GEMM A operand, lo part
__device__ __nv_bfloat16 g_Bhi[CC * CC];   // GEMM B operand [N][K], hi
__device__ __nv_bfloat16 g_Blo[CC * CC];   // GEMM B operand [N][K], lo
__device__ float g_as[NN];
__device__ float g_ad[NN];
__device__ float g_den[NN];
__device__ float g_e[ET];
__device__ float g_ws[CC];
__device__ float g_wd[CC];

// ---------------- helpers ----------------
__device__ __forceinline__ void redAddV4(float4* addr, float4 v) {
    asm volatile("red.global.add.v4.f32 [%0], {%1, %2, %3, %4};"
                 :: "l"(addr), "f"(v.x), "f"(v.y), "f"(v.z), "f"(v.w)
                 : "memory");
}

__device__ __forceinline__ void cpasync16(void* dst_smem, const void* src, int srcsize) {
    uint32_t d = (uint32_t)__cvta_generic_to_shared(dst_smem);
    asm volatile("cp.async.cg.shared.global [%0], [%1], 16, %2;"
                 :: "r"(d), "l"(src), "r"(srcsize));
}

#define MMA_BF16(d, a, b) \
    asm volatile("mma.sync.aligned.m16n8k16.row.col.f32.bf16.bf16.f32 " \
                 "{%0,%1,%2,%3}, {%4,%5,%6,%7}, {%8,%9}, {%0,%1,%2,%3};" \
                 : "+f"(d[0]), "+f"(d[1]), "+f"(d[2]), "+f"(d[3]) \
                 : "r"(a[0]), "r"(a[1]), "r"(a[2]), "r"(a[3]), "r"(b[0]), "r"(b[1]))

__device__ __forceinline__ void split1(float v, __nv_bfloat16& h, __nv_bfloat16& l) {
    h = __float2bfloat16(v);
    l = __float2bfloat16(v - __bfloat162float(h));
}

// ---------------- init: zero acc buffer + den ----------------
__global__ void init_kernel(float* __restrict__ acc) {
    int tid = blockIdx.x * blockDim.x + threadIdx.x;
    int stride = gridDim.x * blockDim.x;
    float4 z = make_float4(0.f, 0.f, 0.f, 0.f);
    float4* acc4 = (float4*)acc;
    const int n4 = NN * CC / 4;
    for (int i = tid; i < n4; i += stride) acc4[i] = z;
    for (int i = tid; i < NN; i += stride) g_den[i] = 0.f;
}

// ---------------- ws = W @ a_src, wd = W @ a_dst (row dots) ----------------
__global__ void wsd_kernel(const float* __restrict__ W,
                           const float* __restrict__ a_s,
                           const float* __restrict__ a_d) {
    int warp = (blockIdx.x * blockDim.x + threadIdx.x) >> 5;
    int lane = threadIdx.x & 31;
    if (warp >= CC) return;
    const float* row = W + (size_t)warp * CC;
    float s = 0.f, d = 0.f;
#pragma unroll
    for (int k = 0; k < 8; k++) {
        float v = row[lane + 32 * k];
        s = fmaf(v, a_s[lane + 32 * k], s);
        d = fmaf(v, a_d[lane + 32 * k], d);
    }
#pragma unroll
    for (int off = 16; off > 0; off >>= 1) {
        s += __shfl_xor_sync(0xffffffff, s, off);
        d += __shfl_xor_sync(0xffffffff, d, off);
    }
    if (lane == 0) { g_ws[warp] = s; g_wd[warp] = d; }
}

// ---------------- warp-per-row: split fp32 -> bf16 hi/lo + alphas ---------
// alpha_src[r] = x[r,:] @ ws,  alpha_dst[r] = x[r,:] @ wd
__global__ __launch_bounds__(256)
void split_x_alpha_kernel(const float* __restrict__ X) {
    int warp = (blockIdx.x * blockDim.x + threadIdx.x) >> 5;
    int lane = threadIdx.x & 31;
    if (warp >= NN) return;
    const float4* xr = (const float4*)(X + (size_t)warp * CC);
    const float4* ws4 = (const float4*)g_ws;
    const float4* wd4 = (const float4*)g_wd;
    __nv_bfloat162* Hr = (__nv_bfloat162*)(g_Ahi + (size_t)warp * CC);
    __nv_bfloat162* Lr = (__nv_bfloat162*)(g_Alo + (size_t)warp * CC);
    float s = 0.f, d = 0.f;
#pragma unroll
    for (int i = 0; i < 2; i++) {
        int idx = lane + 32 * i;
        float4 v = xr[idx];
        float4 a = ws4[idx];
        float4 b = wd4[idx];
        s += v.x*a.x + v.y*a.y + v.z*a.z + v.w*a.w;
        d += v.x*b.x + v.y*b.y + v.z*b.z + v.w*b.w;
        __nv_bfloat16 h0,h1,h2,h3,l0,l1,l2,l3;
        split1(v.x,h0,l0); split1(v.y,h1,l1); split1(v.z,h2,l2); split1(v.w,h3,l3);
        Hr[2*idx]   = __nv_bfloat162(h0,h1);
        Hr[2*idx+1] = __nv_bfloat162(h2,h3);
        Lr[2*idx]   = __nv_bfloat162(l0,l1);
        Lr[2*idx+1] = __nv_bfloat162(l2,l3);
    }
#pragma unroll
    for (int off = 16; off > 0; off >>= 1) {
        s += __shfl_xor_sync(0xffffffff, s, off);
        d += __shfl_xor_sync(0xffffffff, d, off);
    }
    if (lane == 0) { g_as[warp] = s; g_ad[warp] = d; }
}

// ---------------- warp-per-row: bias+relu+split (+ alphas via ws/wd) ------
__global__ __launch_bounds__(256)
void bias_relu_alpha_split_kernel(const float* __restrict__ acc,
                                  const float* __restrict__ bias,
                                  int do_alpha) {
    int warp = (blockIdx.x * blockDim.x + threadIdx.x) >> 5;
    int lane = threadIdx.x & 31;
    if (warp >= NN) return;
    const float4* xr = (const float4*)(acc + (size_t)warp * CC);
    const float4* bias4 = (const float4*)bias;
    const float4* ws4 = (const float4*)g_ws;
    const float4* wd4 = (const float4*)g_wd;
    __nv_bfloat162* Hr = (__nv_bfloat162*)(g_Ahi + (size_t)warp * CC);
    __nv_bfloat162* Lr = (__nv_bfloat162*)(g_Alo + (size_t)warp * CC);
    float s = 0.f, d = 0.f;
#pragma unroll
    for (int i = 0; i < 2; i++) {
        int idx = lane + 32 * i;
        float4 v = xr[idx];
        float4 bb = bias4[idx];
        v.x = fmaxf(v.x + bb.x, 0.f);
        v.y = fmaxf(v.y + bb.y, 0.f);
        v.z = fmaxf(v.z + bb.z, 0.f);
        v.w = fmaxf(v.w + bb.w, 0.f);
        if (do_alpha) {
            float4 a = ws4[idx];
            float4 b = wd4[idx];
            s += v.x*a.x + v.y*a.y + v.z*a.z + v.w*a.w;
            d += v.x*b.x + v.y*b.y + v.z*b.z + v.w*b.w;
        }
        __nv_bfloat16 h0,h1,h2,h3,l0,l1,l2,l3;
        split1(v.x,h0,l0); split1(v.y,h1,l1); split1(v.z,h2,l2); split1(v.w,h3,l3);
        Hr[2*idx]   = __nv_bfloat162(h0,h1);
        Hr[2*idx+1] = __nv_bfloat162(h2,h3);
        Lr[2*idx]   = __nv_bfloat162(l0,l1);
        Lr[2*idx+1] = __nv_bfloat162(l2,l3);
    }
    if (do_alpha) {
#pragma unroll
        for (int off = 16; off > 0; off >>= 1) {
            s += __shfl_xor_sync(0xffffffff, s, off);
            d += __shfl_xor_sync(0xffffffff, d, off);
        }
        if (lane == 0) { g_as[warp] = s; g_ad[warp] = d; }
    }
}

// weight split: W [K,N] -> Bt [N,K] (transpose), or Wl [N,K] -> direct copy-split
__global__ void splitW_T_kernel(const float* __restrict__ W) {
    int n = blockIdx.x, k = threadIdx.x;
    float v = W[k * CC + n];
    split1(v, g_Bhi[n * CC + k], g_Blo[n * CC + k]);
}
__global__ void splitW_N_kernel(const float* __restrict__ W) {
    int n = blockIdx.x, k = threadIdx.x;
    float v = W[n * CC + k];
    split1(v, g_Bhi[n * CC + k], g_Blo[n * CC + k]);
}

// ---------------- bf16-split tensor-core GEMM ----------------
// C[M,256] = Ahi@Bhi^T + Ahi@Blo^T + Alo@Bhi^T  (B stored [N,K])
// 128x128 CTA tile, 8 warps (2M x 4N), warp tile 64x32, BK=32, 2-stage cp.async.
#define SPAD 40            // smem row stride in bf16 elems (32 + 8 pad)
#define STAGE_E (128*SPAD) // 5120 elems per matrix per stage

__global__ __launch_bounds__(256, 2)
void gemm_bf16split(const __nv_bfloat16* __restrict__ Ah,
                    const __nv_bfloat16* __restrict__ Al,
                    const __nv_bfloat16* __restrict__ Bh,
                    const __nv_bfloat16* __restrict__ Bl,
                    float* __restrict__ C,
                    const float* __restrict__ bias,
                    int M, int relu) {
    extern __shared__ __nv_bfloat16 sm[];
    __nv_bfloat16* sAh = sm;
    __nv_bfloat16* sAl = sm + 2 * STAGE_E;
    __nv_bfloat16* sBh = sm + 4 * STAGE_E;
    __nv_bfloat16* sBl = sm + 6 * STAGE_E;

    const int tid = threadIdx.x;
    const int lane = tid & 31;
    const int wid = tid >> 5;
    const int warpM = wid & 1;       // 0..1, 64 rows each
    const int warpN = wid >> 1;      // 0..3, 32 cols each
    const int g = lane >> 2;
    const int t = lane & 3;
    const int M0 = blockIdx.y * 128;
    const int colBase = blockIdx.x * 128;

    const int row0 = tid >> 2;             // chunk set 0: rows 0..63
    const int cc0  = tid & 3;
    const int row1 = (tid + 256) >> 2;     // chunk set 1: rows 64..127

    float acc[4][4][4];
#pragma unroll
    for (int i = 0; i < 4; i++)
#pragma unroll
        for (int j = 0; j < 4; j++)
#pragma unroll
            for (int k = 0; k < 4; k++) acc[i][j][k] = 0.f;

    auto loadTiles = [&](int stage, int kt) {
        __nv_bfloat16* dAh = sAh + stage * STAGE_E;
        __nv_bfloat16* dAl = sAl + stage * STAGE_E;
        __nv_bfloat16* dBh = sBh + stage * STAGE_E;
        __nv_bfloat16* dBl = sBl + stage * STAGE_E;
        {
            int gr = M0 + row0;
            int sz = (gr < M) ? 16 : 0;
            int gro = (gr < M) ? gr : 0;
            size_t go = (size_t)gro * CC + kt + cc0 * 8;
            cpasync16(dAh + row0 * SPAD + cc0 * 8, Ah + go, sz);
            cpasync16(dAl + row0 * SPAD + cc0 * 8, Al + go, sz);
        }
        {
            int gr = M0 + row1;
            int sz = (gr < M) ? 16 : 0;
            int gro = (gr < M) ? gr : 0;
            size_t go = (size_t)gro * CC + kt + cc0 * 8;
            cpasync16(dAh + row1 * SPAD + cc0 * 8, Ah + go, sz);
            cpasync16(dAl + row1 * SPAD + cc0 * 8, Al + go, sz);
        }
        {
            size_t go = (size_t)(colBase + row0) * CC + kt + cc0 * 8;
            cpasync16(dBh + row0 * SPAD + cc0 * 8, Bh + go, 16);
            cpasync16(dBl + row0 * SPAD + cc0 * 8, Bl + go, 16);
            size_t go1 = (size_t)(colBase + row1) * CC + kt + cc0 * 8;
            cpasync16(dBh + row1 * SPAD + cc0 * 8, Bh + go1, 16);
            cpasync16(dBl + row1 * SPAD + cc0 * 8, Bl + go1, 16);
        }
    };

    loadTiles(0, 0);
    asm volatile("cp.async.commit_group;");

    const int arow = warpM * 64 + g;
    const int n0 = warpN * 32 + g;

    for (int kt = 0; kt < 8; kt++) {
        if (kt < 7) {
            loadTiles((kt + 1) & 1, (kt + 1) * 32);
            asm volatile("cp.async.commit_group;");
            asm volatile("cp.async.wait_group 1;");
        } else {
            asm volatile("cp.async.wait_group 0;");
        }
        __syncthreads();

        int stage = kt & 1;
        const __nv_bfloat16* bAh = sAh + stage * STAGE_E;
        const __nv_bfloat16* bAl = sAl + stage * STAGE_E;
        const __nv_bfloat16* bBh = sBh + stage * STAGE_E;
        const __nv_bfloat16* bBl = sBl + stage * STAGE_E;

#pragma unroll
        for (int ks = 0; ks < 32; ks += 16) {
            uint32_t af[4][4], bhf[4][2], blf[4][2];
            const uint32_t* pa = (const uint32_t*)(bAh + arow * SPAD + ks + 2 * t);
#pragma unroll
            for (int mt = 0; mt < 4; mt++) {
                af[mt][0] = pa[mt * 320];
                af[mt][1] = pa[mt * 320 + 160];
                af[mt][2] = pa[mt * 320 + 4];
                af[mt][3] = pa[mt * 320 + 164];
            }
            const uint32_t* pbh = (const uint32_t*)(bBh + n0 * SPAD + ks + 2 * t);
            const uint32_t* pbl = (const uint32_t*)(bBl + n0 * SPAD + ks + 2 * t);
#pragma unroll
            for (int nt = 0; nt < 4; nt++) {
                bhf[nt][0] = pbh[nt * 160];
                bhf[nt][1] = pbh[nt * 160 + 4];
                blf[nt][0] = pbl[nt * 160];
                blf[nt][1] = pbl[nt * 160 + 4];
            }
#pragma unroll
            for (int mt = 0; mt < 4; mt++)
#pragma unroll
                for (int nt = 0; nt < 4; nt++)
                    MMA_BF16(acc[mt][nt], af[mt], bhf[nt]);
#pragma unroll
            for (int mt = 0; mt < 4; mt++)
#pragma unroll
                for (int nt = 0; nt < 4; nt++)
                    MMA_BF16(acc[mt][nt], af[mt], blf[nt]);
            const uint32_t* pal = (const uint32_t*)(bAl + arow * SPAD + ks + 2 * t);
#pragma unroll
            for (int mt = 0; mt < 4; mt++) {
                af[mt][0] = pal[mt * 320];
                af[mt][1] = pal[mt * 320 + 160];
                af[mt][2] = pal[mt * 320 + 4];
                af[mt][3] = pal[mt * 320 + 164];
            }
#pragma unroll
            for (int mt = 0; mt < 4; mt++)
#pragma unroll
                for (int nt = 0; nt < 4; nt++)
                    MMA_BF16(acc[mt][nt], af[mt], bhf[nt]);
        }
        __syncthreads();
    }

#pragma unroll
    for (int mt = 0; mt < 4; mt++) {
        int r0 = M0 + warpM * 64 + mt * 16 + g;
#pragma unroll
        for (int nt = 0; nt < 4; nt++) {
            int c0 = colBase + warpN * 32 + nt * 8 + 2 * t;
            float2 v01 = make_float2(acc[mt][nt][0], acc[mt][nt][1]);
            float2 v23 = make_float2(acc[mt][nt][2], acc[mt][nt][3]);
            if (bias) {
                float b0 = bias[c0], b1 = bias[c0 + 1];
                v01.x += b0; v01.y += b1;
                v23.x += b0; v23.y += b1;
            }
            if (relu) {
                v01.x = fmaxf(v01.x, 0.f); v01.y = fmaxf(v01.y, 0.f);
                v23.x = fmaxf(v23.x, 0.f); v23.y = fmaxf(v23.y, 0.f);
            }
            if (r0 < M)     *(float2*)(C + (size_t)r0 * CC + c0) = v01;
            if (r0 + 8 < M) *(float2*)(C + (size_t)(r0 + 8) * CC + c0) = v23;
        }
    }
}

// ---------------- edge softmax: e=leaky(as+ad); ex=exp(e); den+=ex --------
// (no max subtraction: |alpha| is O(1), exp cannot overflow; w is identical)
__global__ void edge_softmax_kernel(const int* __restrict__ src,
                                    const int* __restrict__ dst) {
    int i = blockIdx.x * blockDim.x + threadIdx.x;
    if (i >= ET) return;
    int s, d;
    if (i < EE) { s = src[i]; d = dst[i]; }
    else        { s = d = i - EE; }
    float e = g_as[s] + g_ad[d];
    e = (e > 0.f) ? e : 0.2f * e;
    float ex = expf(e);
    g_e[i] = ex;
    atomicAdd(&g_den[d], ex);
}

// ---------------- edge aggregate: out[dst] += h[src] * (ex/den[dst]) ------
__global__ __launch_bounds__(256)
void edge_aggr_kernel(const int* __restrict__ src,
                      const int* __restrict__ dst,
                      const float* __restrict__ h,
                      float* __restrict__ out) {
    int warp = (blockIdx.x * blockDim.x + threadIdx.x) >> 5;
    int lane = threadIdx.x & 31;
    if (warp >= ET) return;
    int s, d;
    if (warp < EE) { s = src[warp]; d = dst[warp]; }
    else           { s = d = warp - EE; }
    float w = g_e[warp] / g_den[d];
    const float4* hp = (const float4*)(h + (size_t)s * CC);
    float4* op = (float4*)(out + (size_t)d * CC);
#pragma unroll
    for (int j = 0; j < 2; j++) {
        float4 v = __ldg(hp + lane + j * 32);
        v.x *= w; v.y *= w; v.z *= w; v.w *= w;
        redAddV4(op + lane + j * 32, v);
    }
}

// ---------------- launch ----------------
extern "C" void kernel_launch(void* const* d_in, const int* in_sizes, int n_in,
                              void* d_out, int out_size) {
    const float* x    = (const float*)d_in[0];
    const int*   ei   = (const int*)d_in[1];
    const float* W1   = (const float*)d_in[2];
    const float* a1s  = (const float*)d_in[3];
    const float* a1d  = (const float*)d_in[4];
    const float* b1   = (const float*)d_in[5];
    const float* W2   = (const float*)d_in[6];
    const float* a2s  = (const float*)d_in[7];
    const float* a2d  = (const float*)d_in[8];
    const float* b2   = (const float*)d_in[9];
    const float* Wl   = (const float*)d_in[10];
    const float* bl   = (const float*)d_in[11];
    float* out = (float*)d_out;

    const int* src = ei;
    const int* dst = ei + EE;

    float *ph, *pacc;
    __nv_bfloat16 *pAh, *pAl, *pBh, *pBl;
    cudaGetSymbolAddress((void**)&ph,   g_h);
    cudaGetSymbolAddress((void**)&pacc, g_acc);
    cudaGetSymbolAddress((void**)&pAh,  g_Ahi);
    cudaGetSymbolAddress((void**)&pAl,  g_Alo);
    cudaGetSymbolAddress((void**)&pBh,  g_Bhi);
    cudaGetSymbolAddress((void**)&pBl,  g_Blo);

    static const int SMEM_BYTES = 8 * STAGE_E * 2;  // 81920
    cudaFuncSetAttribute(gemm_bf16split,
                         cudaFuncAttributeMaxDynamicSharedMemorySize, SMEM_BYTES);

    dim3 gemmGrid(2, (NN + 127) / 128);
    int edgeBlocks = (ET + 255) / 256;
    int aggrBlocks = (ET * 32 + 255) / 256;
    int rowBlocks = (NN + 7) / 8;   // warp-per-row kernels

    // ---- layer 1 ----
    wsd_kernel<<<32, 256>>>(W1, a1s, a1d);
    split_x_alpha_kernel<<<rowBlocks, 256>>>(x);
    splitW_T_kernel<<<CC, CC>>>(W1);
    gemm_bf16split<<<gemmGrid, 256, SMEM_BYTES>>>(pAh, pAl, pBh, pBl, ph, nullptr, NN, 0);
    init_kernel<<<2048, 256>>>(pacc);
    edge_softmax_kernel<<<edgeBlocks, 256>>>(src, dst);
    edge_aggr_kernel<<<aggrBlocks, 256>>>(src, dst, ph, pacc);

    // ---- layer 2 ----
    wsd_kernel<<<32, 256>>>(W2, a2s, a2d);
    bias_relu_alpha_split_kernel<<<rowBlocks, 256>>>(pacc, b1, 1);
    splitW_T_kernel<<<CC, CC>>>(W2);
    gemm_bf16split<<<gemmGrid, 256, SMEM_BYTES>>>(pAh, pAl, pBh, pBl, ph, nullptr, NN, 0);
    init_kernel<<<2048, 256>>>(pacc);
    edge_softmax_kernel<<<edgeBlocks, 256>>>(src, dst);
    edge_aggr_kernel<<<aggrBlocks, 256>>>(src, dst, ph, pacc);

    // ---- final linear: out = relu-free (acc+b2 relu'd) @ Wl^T + bl ----
    bias_relu_alpha_split_kernel<<<rowBlocks, 256>>>(pacc, b2, 0);
    splitW_N_kernel<<<CC, CC>>>(Wl);
    gemm_bf16split<<<gemmGrid, 256, SMEM_BYTES>>>(pAh, pAl, pBh, pBl, out, bl, NN, 0);
}

// round 6
// speedup vs baseline: 1.8146x; 1.0149x over previous
#include <cuda_runtime.h>
#include <cuda_bf16.h>
#include <cstdint>
#include <math.h>

#define NN 50000
#define EE 300000
#define ET (EE + NN)
#define CC 256

// ---------------- scratch (device globals) ----------------
__device__ float g_h[NN * CC];
__device__ float g_acc[NN * CC];
__device__ __nv_bfloat16 g_Ahi[NN * CC];
__device__ __nv_bfloat16 g_Alo[NN * CC];
__device__ __nv_bfloat16 g_Bhi[CC * CC];   // [N][K]
__device__ __nv_bfloat16 g_Blo[CC * CC];
__device__ float g_as[NN];
__device__ float g_ad[NN];
__device__ float g_den[NN];
__device__ float g_e[ET];
__device__ float g_ws[CC];
__device__ float g_wd[CC];

// ---------------- helpers ----------------
__device__ __forceinline__ void redAddV4(float4* addr, float4 v) {
    asm volatile("red.global.add.v4.f32 [%0], {%1, %2, %3, %4};"
                 :: "l"(addr), "f"(v.x), "f"(v.y), "f"(v.z), "f"(v.w)
                 : "memory");
}

__device__ __forceinline__ void cpasync16(void* dst_smem, const void* src, int srcsize) {
    uint32_t d = (uint32_t)__cvta_generic_to_shared(dst_smem);
    asm volatile("cp.async.cg.shared.global [%0], [%1], 16, %2;"
                 :: "r"(d), "l"(src), "r"(srcsize));
}

__device__ __forceinline__ uint32_t smem_u32(const void* p) {
    return (uint32_t)__cvta_generic_to_shared(p);
}

#define MMA_BF16(d, a, b) \
    asm volatile("mma.sync.aligned.m16n8k16.row.col.f32.bf16.bf16.f32 " \
                 "{%0,%1,%2,%3}, {%4,%5,%6,%7}, {%8,%9}, {%0,%1,%2,%3};" \
                 : "+f"(d[0]), "+f"(d[1]), "+f"(d[2]), "+f"(d[3]) \
                 : "r"(a[0]), "r"(a[1]), "r"(a[2]), "r"(a[3]), "r"(b[0]), "r"(b[1]))

#define LDMX4(r0, r1, r2, r3, addr) \
    asm volatile("ldmatrix.sync.aligned.m8n8.x4.shared.b16 {%0,%1,%2,%3}, [%4];" \
                 : "=r"(r0), "=r"(r1), "=r"(r2), "=r"(r3) : "r"(addr))

__device__ __forceinline__ void split1(float v, __nv_bfloat16& h, __nv_bfloat16& l) {
    h = __float2bfloat16(v);
    l = __float2bfloat16(v - __bfloat162float(h));
}

// ---------------- init: zero acc buffer + den ----------------
__global__ void init_kernel(float* __restrict__ acc) {
    int tid = blockIdx.x * blockDim.x + threadIdx.x;
    int stride = gridDim.x * blockDim.x;
    float4 z = make_float4(0.f, 0.f, 0.f, 0.f);
    float4* acc4 = (float4*)acc;
    const int n4 = NN * CC / 4;
    for (int i = tid; i < n4; i += stride) acc4[i] = z;
    for (int i = tid; i < NN; i += stride) g_den[i] = 0.f;
}

// ---------------- ws = W @ a_src, wd = W @ a_dst ----------------
__global__ void wsd_kernel(const float* __restrict__ W,
                           const float* __restrict__ a_s,
                           const float* __restrict__ a_d) {
    int warp = (blockIdx.x * blockDim.x + threadIdx.x) >> 5;
    int lane = threadIdx.x & 31;
    if (warp >= CC) return;
    const float* row = W + (size_t)warp * CC;
    float s = 0.f, d = 0.f;
#pragma unroll
    for (int k = 0; k < 8; k++) {
        float v = row[lane + 32 * k];
        s = fmaf(v, a_s[lane + 32 * k], s);
        d = fmaf(v, a_d[lane + 32 * k], d);
    }
#pragma unroll
    for (int off = 16; off > 0; off >>= 1) {
        s += __shfl_xor_sync(0xffffffff, s, off);
        d += __shfl_xor_sync(0xffffffff, d, off);
    }
    if (lane == 0) { g_ws[warp] = s; g_wd[warp] = d; }
}

// ---------------- warp-per-row: split fp32 -> bf16 hi/lo + alphas ---------
__global__ __launch_bounds__(256)
void split_x_alpha_kernel(const float* __restrict__ X) {
    int warp = (blockIdx.x * blockDim.x + threadIdx.x) >> 5;
    int lane = threadIdx.x & 31;
    if (warp >= NN) return;
    const float4* xr = (const float4*)(X + (size_t)warp * CC);
    const float4* ws4 = (const float4*)g_ws;
    const float4* wd4 = (const float4*)g_wd;
    __nv_bfloat162* Hr = (__nv_bfloat162*)(g_Ahi + (size_t)warp * CC);
    __nv_bfloat162* Lr = (__nv_bfloat162*)(g_Alo + (size_t)warp * CC);
    float s = 0.f, d = 0.f;
#pragma unroll
    for (int i = 0; i < 2; i++) {
        int idx = lane + 32 * i;
        float4 v = xr[idx];
        float4 a = ws4[idx];
        float4 b = wd4[idx];
        s += v.x*a.x + v.y*a.y + v.z*a.z + v.w*a.w;
        d += v.x*b.x + v.y*b.y + v.z*b.z + v.w*b.w;
        __nv_bfloat16 h0,h1,h2,h3,l0,l1,l2,l3;
        split1(v.x,h0,l0); split1(v.y,h1,l1); split1(v.z,h2,l2); split1(v.w,h3,l3);
        Hr[2*idx]   = __nv_bfloat162(h0,h1);
        Hr[2*idx+1] = __nv_bfloat162(h2,h3);
        Lr[2*idx]   = __nv_bfloat162(l0,l1);
        Lr[2*idx+1] = __nv_bfloat162(l2,l3);
    }
#pragma unroll
    for (int off = 16; off > 0; off >>= 1) {
        s += __shfl_xor_sync(0xffffffff, s, off);
        d += __shfl_xor_sync(0xffffffff, d, off);
    }
    if (lane == 0) { g_as[warp] = s; g_ad[warp] = d; }
}

// ---------------- warp-per-row: bias+relu+split (+ alphas) ------
__global__ __launch_bounds__(256)
void bias_relu_alpha_split_kernel(const float* __restrict__ acc,
                                  const float* __restrict__ bias,
                                  int do_alpha) {
    int warp = (blockIdx.x * blockDim.x + threadIdx.x) >> 5;
    int lane = threadIdx.x & 31;
    if (warp >= NN) return;
    const float4* xr = (const float4*)(acc + (size_t)warp * CC);
    const float4* bias4 = (const float4*)bias;
    const float4* ws4 = (const float4*)g_ws;
    const float4* wd4 = (const float4*)g_wd;
    __nv_bfloat162* Hr = (__nv_bfloat162*)(g_Ahi + (size_t)warp * CC);
    __nv_bfloat162* Lr = (__nv_bfloat162*)(g_Alo + (size_t)warp * CC);
    float s = 0.f, d = 0.f;
#pragma unroll
    for (int i = 0; i < 2; i++) {
        int idx = lane + 32 * i;
        float4 v = xr[idx];
        float4 bb = bias4[idx];
        v.x = fmaxf(v.x + bb.x, 0.f);
        v.y = fmaxf(v.y + bb.y, 0.f);
        v.z = fmaxf(v.z + bb.z, 0.f);
        v.w = fmaxf(v.w + bb.w, 0.f);
        if (do_alpha) {
            float4 a = ws4[idx];
            float4 b = wd4[idx];
            s += v.x*a.x + v.y*a.y + v.z*a.z + v.w*a.w;
            d += v.x*b.x + v.y*b.y + v.z*b.z + v.w*b.w;
        }
        __nv_bfloat16 h0,h1,h2,h3,l0,l1,l2,l3;
        split1(v.x,h0,l0); split1(v.y,h1,l1); split1(v.z,h2,l2); split1(v.w,h3,l3);
        Hr[2*idx]   = __nv_bfloat162(h0,h1);
        Hr[2*idx+1] = __nv_bfloat162(h2,h3);
        Lr[2*idx]   = __nv_bfloat162(l0,l1);
        Lr[2*idx+1] = __nv_bfloat162(l2,l3);
    }
    if (do_alpha) {
#pragma unroll
        for (int off = 16; off > 0; off >>= 1) {
            s += __shfl_xor_sync(0xffffffff, s, off);
            d += __shfl_xor_sync(0xffffffff, d, off);
        }
        if (lane == 0) { g_as[warp] = s; g_ad[warp] = d; }
    }
}

// weight split
__global__ void splitW_T_kernel(const float* __restrict__ W) {
    int n = blockIdx.x, k = threadIdx.x;
    float v = W[k * CC + n];
    split1(v, g_Bhi[n * CC + k], g_Blo[n * CC + k]);
}
__global__ void splitW_N_kernel(const float* __restrict__ W) {
    int n = blockIdx.x, k = threadIdx.x;
    float v = W[n * CC + k];
    split1(v, g_Bhi[n * CC + k], g_Blo[n * CC + k]);
}

// ---------------- bf16-split tensor-core GEMM (ldmatrix fragments) --------
// C[M,256] = Ahi@Bhi^T + Ahi@Blo^T + Alo@Bhi^T  (B stored [N,K])
// 128x128 CTA tile, 8 warps (2M x 4N), warp tile 64x32, BK=32, 2-stage cp.async.
#define SPAD 40            // smem row stride in bf16 elems (32 + 8 pad)
#define STAGE_E (128*SPAD) // 5120 elems per matrix per stage

__global__ __launch_bounds__(256, 2)
void gemm_bf16split(const __nv_bfloat16* __restrict__ Ah,
                    const __nv_bfloat16* __restrict__ Al,
                    const __nv_bfloat16* __restrict__ Bh,
                    const __nv_bfloat16* __restrict__ Bl,
                    float* __restrict__ C,
                    const float* __restrict__ bias,
                    int M, int relu) {
    extern __shared__ __nv_bfloat16 sm[];
    __nv_bfloat16* sAh = sm;
    __nv_bfloat16* sAl = sm + 2 * STAGE_E;
    __nv_bfloat16* sBh = sm + 4 * STAGE_E;
    __nv_bfloat16* sBl = sm + 6 * STAGE_E;

    const int tid = threadIdx.x;
    const int lane = tid & 31;
    const int wid = tid >> 5;
    const int warpM = wid & 1;       // 0..1, 64 rows each
    const int warpN = wid >> 1;      // 0..3, 32 cols each
    const int g = lane >> 2;
    const int t = lane & 3;
    const int M0 = blockIdx.y * 128;
    const int colBase = blockIdx.x * 128;

    const int row0 = tid >> 2;             // chunk set 0: rows 0..63
    const int cc0  = tid & 3;
    const int row1 = (tid + 256) >> 2;     // chunk set 1: rows 64..127

    // ldmatrix per-lane address components (in elements)
    // A: 16x16 tile, matrices: [rows0-7,k0][rows8-15,k0][rows0-7,k8][rows8-15,k8]
    const int a_row_l = warpM * 64 + (lane & 15);
    const int a_col_l = (lane >> 4) * 8;
    // B: matrices: [n0-7,k0][n0-7,k8][n8-15,k0][n8-15,k8]
    const int b_row_l = warpN * 32 + ((lane >> 4) & 1) * 8 + (lane & 7);
    const int b_col_l = ((lane >> 3) & 1) * 8;

    float acc[4][4][4];
#pragma unroll
    for (int i = 0; i < 4; i++)
#pragma unroll
        for (int j = 0; j < 4; j++)
#pragma unroll
            for (int k = 0; k < 4; k++) acc[i][j][k] = 0.f;

    auto loadTiles = [&](int stage, int kt) {
        __nv_bfloat16* dAh = sAh + stage * STAGE_E;
        __nv_bfloat16* dAl = sAl + stage * STAGE_E;
        __nv_bfloat16* dBh = sBh + stage * STAGE_E;
        __nv_bfloat16* dBl = sBl + stage * STAGE_E;
        {
            int gr = M0 + row0;
            int sz = (gr < M) ? 16 : 0;
            int gro = (gr < M) ? gr : 0;
            size_t go = (size_t)gro * CC + kt + cc0 * 8;
            cpasync16(dAh + row0 * SPAD + cc0 * 8, Ah + go, sz);
            cpasync16(dAl + row0 * SPAD + cc0 * 8, Al + go, sz);
        }
        {
            int gr = M0 + row1;
            int sz = (gr < M) ? 16 : 0;
            int gro = (gr < M) ? gr : 0;
            size_t go = (size_t)gro * CC + kt + cc0 * 8;
            cpasync16(dAh + row1 * SPAD + cc0 * 8, Ah + go, sz);
            cpasync16(dAl + row1 * SPAD + cc0 * 8, Al + go, sz);
        }
        {
            size_t go = (size_t)(colBase + row0) * CC + kt + cc0 * 8;
            cpasync16(dBh + row0 * SPAD + cc0 * 8, Bh + go, 16);
            cpasync16(dBl + row0 * SPAD + cc0 * 8, Bl + go, 16);
            size_t go1 = (size_t)(colBase + row1) * CC + kt + cc0 * 8;
            cpasync16(dBh + row1 * SPAD + cc0 * 8, Bh + go1, 16);
            cpasync16(dBl + row1 * SPAD + cc0 * 8, Bl + go1, 16);
        }
    };

    loadTiles(0, 0);
    asm volatile("cp.async.commit_group;");

    for (int kt = 0; kt < 8; kt++) {
        if (kt < 7) {
            loadTiles((kt + 1) & 1, (kt + 1) * 32);
            asm volatile("cp.async.commit_group;");
            asm volatile("cp.async.wait_group 1;");
        } else {
            asm volatile("cp.async.wait_group 0;");
        }
        __syncthreads();

        int stage = kt & 1;
        const uint32_t uAh = smem_u32(sAh + stage * STAGE_E);
        const uint32_t uAl = smem_u32(sAl + stage * STAGE_E);
        const uint32_t uBh = smem_u32(sBh + stage * STAGE_E);
        const uint32_t uBl = smem_u32(sBl + stage * STAGE_E);

#pragma unroll
        for (int ks = 0; ks < 32; ks += 16) {
            uint32_t af[4][4], bhf[4][2], blf[4][2];
            const uint32_t aoff = (uint32_t)((a_row_l * SPAD + ks + a_col_l) * 2);
            const uint32_t boff = (uint32_t)((b_row_l * SPAD + ks + b_col_l) * 2);
#pragma unroll
            for (int mt = 0; mt < 4; mt++)
                LDMX4(af[mt][0], af[mt][1], af[mt][2], af[mt][3],
                      uAh + aoff + mt * (16 * SPAD * 2));
#pragma unroll
            for (int np = 0; np < 2; np++) {
                LDMX4(bhf[2*np][0], bhf[2*np][1], bhf[2*np+1][0], bhf[2*np+1][1],
                      uBh + boff + np * (16 * SPAD * 2));
                LDMX4(blf[2*np][0], blf[2*np][1], blf[2*np+1][0], blf[2*np+1][1],
                      uBl + boff + np * (16 * SPAD * 2));
            }
            // pass 1: Ahi * Bhi
#pragma unroll
            for (int mt = 0; mt < 4; mt++)
#pragma unroll
                for (int nt = 0; nt < 4; nt++)
                    MMA_BF16(acc[mt][nt], af[mt], bhf[nt]);
            // pass 2: Ahi * Blo
#pragma unroll
            for (int mt = 0; mt < 4; mt++)
#pragma unroll
                for (int nt = 0; nt < 4; nt++)
                    MMA_BF16(acc[mt][nt], af[mt], blf[nt]);
            // pass 3: Alo * Bhi
#pragma unroll
            for (int mt = 0; mt < 4; mt++)
                LDMX4(af[mt][0], af[mt][1], af[mt][2], af[mt][3],
                      uAl + aoff + mt * (16 * SPAD * 2));
#pragma unroll
            for (int mt = 0; mt < 4; mt++)
#pragma unroll
                for (int nt = 0; nt < 4; nt++)
                    MMA_BF16(acc[mt][nt], af[mt], bhf[nt]);
        }
        __syncthreads();
    }

#pragma unroll
    for (int mt = 0; mt < 4; mt++) {
        int r0 = M0 + warpM * 64 + mt * 16 + g;
#pragma unroll
        for (int nt = 0; nt < 4; nt++) {
            int c0 = colBase + warpN * 32 + nt * 8 + 2 * t;
            float2 v01 = make_float2(acc[mt][nt][0], acc[mt][nt][1]);
            float2 v23 = make_float2(acc[mt][nt][2], acc[mt][nt][3]);
            if (bias) {
                float b0 = bias[c0], b1 = bias[c0 + 1];
                v01.x += b0; v01.y += b1;
                v23.x += b0; v23.y += b1;
            }
            if (relu) {
                v01.x = fmaxf(v01.x, 0.f); v01.y = fmaxf(v01.y, 0.f);
                v23.x = fmaxf(v23.x, 0.f); v23.y = fmaxf(v23.y, 0.f);
            }
            if (r0 < M)     *(float2*)(C + (size_t)r0 * CC + c0) = v01;
            if (r0 + 8 < M) *(float2*)(C + (size_t)(r0 + 8) * CC + c0) = v23;
        }
    }
}

// ---------------- edge softmax ----------------
__global__ void edge_softmax_kernel(const int* __restrict__ src,
                                    const int* __restrict__ dst) {
    int i = blockIdx.x * blockDim.x + threadIdx.x;
    if (i >= ET) return;
    int s, d;
    if (i < EE) { s = src[i]; d = dst[i]; }
    else        { s = d = i - EE; }
    float e = g_as[s] + g_ad[d];
    e = (e > 0.f) ? e : 0.2f * e;
    float ex = expf(e);
    g_e[i] = ex;
    atomicAdd(&g_den[d], ex);
}

// ---------------- edge aggregate ----------------
__global__ __launch_bounds__(256)
void edge_aggr_kernel(const int* __restrict__ src,
                      const int* __restrict__ dst,
                      const float* __restrict__ h,
                      float* __restrict__ out) {
    int warp = (blockIdx.x * blockDim.x + threadIdx.x) >> 5;
    int lane = threadIdx.x & 31;
    if (warp >= ET) return;
    int s, d;
    if (warp < EE) { s = src[warp]; d = dst[warp]; }
    else           { s = d = warp - EE; }
    float w = g_e[warp] / g_den[d];
    const float4* hp = (const float4*)(h + (size_t)s * CC);
    float4* op = (float4*)(out + (size_t)d * CC);
#pragma unroll
    for (int j = 0; j < 2; j++) {
        float4 v = __ldg(hp + lane + j * 32);
        v.x *= w; v.y *= w; v.z *= w; v.w *= w;
        redAddV4(op + lane + j * 32, v);
    }
}

// ---------------- launch ----------------
extern "C" void kernel_launch(void* const* d_in, const int* in_sizes, int n_in,
                              void* d_out, int out_size) {
    const float* x    = (const float*)d_in[0];
    const int*   ei   = (const int*)d_in[1];
    const float* W1   = (const float*)d_in[2];
    const float* a1s  = (const float*)d_in[3];
    const float* a1d  = (const float*)d_in[4];
    const float* b1   = (const float*)d_in[5];
    const float* W2   = (const float*)d_in[6];
    const float* a2s  = (const float*)d_in[7];
    const float* a2d  = (const float*)d_in[8];
    const float* b2   = (const float*)d_in[9];
    const float* Wl   = (const float*)d_in[10];
    const float* bl   = (const float*)d_in[11];
    float* out = (float*)d_out;

    const int* src = ei;
    const int* dst = ei + EE;

    float *ph, *pacc;
    __nv_bfloat16 *pAh, *pAl, *pBh, *pBl;
    cudaGetSymbolAddress((void**)&ph,   g_h);
    cudaGetSymbolAddress((void**)&pacc, g_acc);
    cudaGetSymbolAddress((void**)&pAh,  g_Ahi);
    cudaGetSymbolAddress((void**)&pAl,  g_Alo);
    cudaGetSymbolAddress((void**)&pBh,  g_Bhi);
    cudaGetSymbolAddress((void**)&pBl,  g_Blo);

    static const int SMEM_BYTES = 8 * STAGE_E * 2;  // 81920
    cudaFuncSetAttribute(gemm_bf16split,
                         cudaFuncAttributeMaxDynamicSharedMemorySize, SMEM_BYTES);

    dim3 gemmGrid(2, (NN + 127) / 128);
    int edgeBlocks = (ET + 255) / 256;
    int aggrBlocks = (ET * 32 + 255) / 256;
    int rowBlocks = (NN + 7) / 8;

    // ---- layer 1 ----
    wsd_kernel<<<32, 256>>>(W1, a1s, a1d);
    split_x_alpha_kernel<<<rowBlocks, 256>>>(x);
    splitW_T_kernel<<<CC, CC>>>(W1);
    gemm_bf16split<<<gemmGrid, 256, SMEM_BYTES>>>(pAh, pAl, pBh, pBl, ph, nullptr, NN, 0);
    init_kernel<<<2048, 256>>>(pacc);
    edge_softmax_kernel<<<edgeBlocks, 256>>>(src, dst);
    edge_aggr_kernel<<<aggrBlocks, 256>>>(src, dst, ph, pacc);

    // ---- layer 2 ----
    wsd_kernel<<<32, 256>>>(W2, a2s, a2d);
    bias_relu_alpha_split_kernel<<<rowBlocks, 256>>>(pacc, b1, 1);
    splitW_T_kernel<<<CC, CC>>>(W2);
    gemm_bf16split<<<gemmGrid, 256, SMEM_BYTES>>>(pAh, pAl, pBh, pBl, ph, nullptr, NN, 0);
    init_kernel<<<2048, 256>>>(pacc);
    edge_softmax_kernel<<<edgeBlocks, 256>>>(src, dst);
    edge_aggr_kernel<<<aggrBlocks, 256>>>(src, dst, ph, pacc);

    // ---- final linear ----
    bias_relu_alpha_split_kernel<<<rowBlocks, 256>>>(pacc, b2, 0);
    splitW_N_kernel<<<CC, CC>>>(Wl);
    gemm_bf16split<<<gemmGrid, 256, SMEM_BYTES>>>(pAh, pAl, pBh, pBl, out, bl, NN, 0);
}

// round 7
// speedup vs baseline: 2.1757x; 1.1990x over previous
#include <cuda_runtime.h>
#include <cuda_bf16.h>
#include <cstdint>
#include <math.h>

#define NN 50000
#define EE 300000
#define ET (EE + NN)
#define CC 256

// ---------------- scratch (device globals) ----------------
__device__ float g_h[NN * CC];
__device__ float g_acc[NN * CC];
__device__ __nv_bfloat16 g_Ahi[NN * CC];
__device__ __nv_bfloat16 g_Alo[NN * CC];
__device__ __nv_bfloat16 g_Bhi[CC * CC];   // [N][K]
__device__ __nv_bfloat16 g_Blo[CC * CC];
__device__ float g_as[NN];
__device__ float g_ad[NN];
__device__ float g_ws[CC];
__device__ float g_wd[CC];
// CSR
__device__ int g_deg[NN];
__device__ int g_rowstart[NN + 1];
__device__ int g_cursor[NN];
__device__ int g_csr_src[ET];
__device__ int g_bsum[256];

// ---------------- helpers ----------------
__device__ __forceinline__ void cpasync16(void* dst_smem, const void* src, int srcsize) {
    uint32_t d = (uint32_t)__cvta_generic_to_shared(dst_smem);
    asm volatile("cp.async.cg.shared.global [%0], [%1], 16, %2;"
                 :: "r"(d), "l"(src), "r"(srcsize));
}

__device__ __forceinline__ uint32_t smem_u32(const void* p) {
    return (uint32_t)__cvta_generic_to_shared(p);
}

#define MMA_BF16(d, a, b) \
    asm volatile("mma.sync.aligned.m16n8k16.row.col.f32.bf16.bf16.f32 " \
                 "{%0,%1,%2,%3}, {%4,%5,%6,%7}, {%8,%9}, {%0,%1,%2,%3};" \
                 : "+f"(d[0]), "+f"(d[1]), "+f"(d[2]), "+f"(d[3]) \
                 : "r"(a[0]), "r"(a[1]), "r"(a[2]), "r"(a[3]), "r"(b[0]), "r"(b[1]))

#define LDMX4(r0, r1, r2, r3, addr) \
    asm volatile("ldmatrix.sync.aligned.m8n8.x4.shared.b16 {%0,%1,%2,%3}, [%4];" \
                 : "=r"(r0), "=r"(r1), "=r"(r2), "=r"(r3) : "r"(addr))

__device__ __forceinline__ void split1(float v, __nv_bfloat16& h, __nv_bfloat16& l) {
    h = __float2bfloat16(v);
    l = __float2bfloat16(v - __bfloat162float(h));
}

// =================== CSR build (once per launch) ===================
#define SCAN_B 256
#define SCAN_G ((NN + SCAN_B - 1) / SCAN_B)   // 196

__global__ void csr_deg_init_kernel() {
    int i = blockIdx.x * blockDim.x + threadIdx.x;
    if (i < NN) g_deg[i] = 1;   // self loop
}

__global__ void csr_count_kernel(const int* __restrict__ dst) {
    int i = blockIdx.x * blockDim.x + threadIdx.x;
    if (i < EE) atomicAdd(&g_deg[dst[i]], 1);
}

__global__ void scan1_kernel() {
    __shared__ int sd[SCAN_B];
    int t = threadIdx.x, i = blockIdx.x * SCAN_B + t;
    int v = (i < NN) ? g_deg[i] : 0;
    sd[t] = v;
    __syncthreads();
#pragma unroll
    for (int off = 1; off < SCAN_B; off <<= 1) {
        int x = (t >= off) ? sd[t - off] : 0;
        __syncthreads();
        sd[t] += x;
        __syncthreads();
    }
    if (i < NN) g_rowstart[i] = sd[t] - v;        // within-block exclusive
    if (t == SCAN_B - 1) g_bsum[blockIdx.x] = sd[t];
}

__global__ void scan2_kernel() {
    __shared__ int sd[SCAN_B];
    int t = threadIdx.x;
    int v = (t < SCAN_G) ? g_bsum[t] : 0;
    sd[t] = v;
    __syncthreads();
#pragma unroll
    for (int off = 1; off < SCAN_B; off <<= 1) {
        int x = (t >= off) ? sd[t - off] : 0;
        __syncthreads();
        sd[t] += x;
        __syncthreads();
    }
    if (t < SCAN_G) g_bsum[t] = sd[t] - v;        // exclusive block offsets
}

__global__ void scan3_kernel() {
    int t = threadIdx.x, i = blockIdx.x * SCAN_B + t;
    if (i < NN) {
        int r = g_rowstart[i] + g_bsum[blockIdx.x];
        g_rowstart[i] = r;
        g_cursor[i] = r;
    }
    if (i == 0) g_rowstart[NN] = ET;
}

__global__ void csr_scatter_kernel(const int* __restrict__ src,
                                   const int* __restrict__ dst) {
    int i = blockIdx.x * blockDim.x + threadIdx.x;
    if (i >= ET) return;
    int s, d;
    if (i < EE) { s = src[i]; d = dst[i]; }
    else        { s = d = i - EE; }
    int pos = atomicAdd(&g_cursor[d], 1);
    g_csr_src[pos] = s;
}

// ---------------- ws = W @ a_src, wd = W @ a_dst ----------------
__global__ void wsd_kernel(const float* __restrict__ W,
                           const float* __restrict__ a_s,
                           const float* __restrict__ a_d) {
    int warp = (blockIdx.x * blockDim.x + threadIdx.x) >> 5;
    int lane = threadIdx.x & 31;
    if (warp >= CC) return;
    const float* row = W + (size_t)warp * CC;
    float s = 0.f, d = 0.f;
#pragma unroll
    for (int k = 0; k < 8; k++) {
        float v = row[lane + 32 * k];
        s = fmaf(v, a_s[lane + 32 * k], s);
        d = fmaf(v, a_d[lane + 32 * k], d);
    }
#pragma unroll
    for (int off = 16; off > 0; off >>= 1) {
        s += __shfl_xor_sync(0xffffffff, s, off);
        d += __shfl_xor_sync(0xffffffff, d, off);
    }
    if (lane == 0) { g_ws[warp] = s; g_wd[warp] = d; }
}

// ---------------- warp-per-row: split fp32 -> bf16 hi/lo + alphas ---------
__global__ __launch_bounds__(256)
void split_x_alpha_kernel(const float* __restrict__ X) {
    int warp = (blockIdx.x * blockDim.x + threadIdx.x) >> 5;
    int lane = threadIdx.x & 31;
    if (warp >= NN) return;
    const float4* xr = (const float4*)(X + (size_t)warp * CC);
    const float4* ws4 = (const float4*)g_ws;
    const float4* wd4 = (const float4*)g_wd;
    __nv_bfloat162* Hr = (__nv_bfloat162*)(g_Ahi + (size_t)warp * CC);
    __nv_bfloat162* Lr = (__nv_bfloat162*)(g_Alo + (size_t)warp * CC);
    float s = 0.f, d = 0.f;
#pragma unroll
    for (int i = 0; i < 2; i++) {
        int idx = lane + 32 * i;
        float4 v = xr[idx];
        float4 a = ws4[idx];
        float4 b = wd4[idx];
        s += v.x*a.x + v.y*a.y + v.z*a.z + v.w*a.w;
        d += v.x*b.x + v.y*b.y + v.z*b.z + v.w*b.w;
        __nv_bfloat16 h0,h1,h2,h3,l0,l1,l2,l3;
        split1(v.x,h0,l0); split1(v.y,h1,l1); split1(v.z,h2,l2); split1(v.w,h3,l3);
        Hr[2*idx]   = __nv_bfloat162(h0,h1);
        Hr[2*idx+1] = __nv_bfloat162(h2,h3);
        Lr[2*idx]   = __nv_bfloat162(l0,l1);
        Lr[2*idx+1] = __nv_bfloat162(l2,l3);
    }
#pragma unroll
    for (int off = 16; off > 0; off >>= 1) {
        s += __shfl_xor_sync(0xffffffff, s, off);
        d += __shfl_xor_sync(0xffffffff, d, off);
    }
    if (lane == 0) { g_as[warp] = s; g_ad[warp] = d; }
}

// ---------------- warp-per-row: bias+relu+split (+ alphas) ------
__global__ __launch_bounds__(256)
void bias_relu_alpha_split_kernel(const float* __restrict__ acc,
                                  const float* __restrict__ bias,
                                  int do_alpha) {
    int warp = (blockIdx.x * blockDim.x + threadIdx.x) >> 5;
    int lane = threadIdx.x & 31;
    if (warp >= NN) return;
    const float4* xr = (const float4*)(acc + (size_t)warp * CC);
    const float4* bias4 = (const float4*)bias;
    const float4* ws4 = (const float4*)g_ws;
    const float4* wd4 = (const float4*)g_wd;
    __nv_bfloat162* Hr = (__nv_bfloat162*)(g_Ahi + (size_t)warp * CC);
    __nv_bfloat162* Lr = (__nv_bfloat162*)(g_Alo + (size_t)warp * CC);
    float s = 0.f, d = 0.f;
#pragma unroll
    for (int i = 0; i < 2; i++) {
        int idx = lane + 32 * i;
        float4 v = xr[idx];
        float4 bb = bias4[idx];
        v.x = fmaxf(v.x + bb.x, 0.f);
        v.y = fmaxf(v.y + bb.y, 0.f);
        v.z = fmaxf(v.z + bb.z, 0.f);
        v.w = fmaxf(v.w + bb.w, 0.f);
        if (do_alpha) {
            float4 a = ws4[idx];
            float4 b = wd4[idx];
            s += v.x*a.x + v.y*a.y + v.z*a.z + v.w*a.w;
            d += v.x*b.x + v.y*b.y + v.z*b.z + v.w*b.w;
        }
        __nv_bfloat16 h0,h1,h2,h3,l0,l1,l2,l3;
        split1(v.x,h0,l0); split1(v.y,h1,l1); split1(v.z,h2,l2); split1(v.w,h3,l3);
        Hr[2*idx]   = __nv_bfloat162(h0,h1);
        Hr[2*idx+1] = __nv_bfloat162(h2,h3);
        Lr[2*idx]   = __nv_bfloat162(l0,l1);
        Lr[2*idx+1] = __nv_bfloat162(l2,l3);
    }
    if (do_alpha) {
#pragma unroll
        for (int off = 16; off > 0; off >>= 1) {
            s += __shfl_xor_sync(0xffffffff, s, off);
            d += __shfl_xor_sync(0xffffffff, d, off);
        }
        if (lane == 0) { g_as[warp] = s; g_ad[warp] = d; }
    }
}

// weight split
__global__ void splitW_T_kernel(const float* __restrict__ W) {
    int n = blockIdx.x, k = threadIdx.x;
    float v = W[k * CC + n];
    split1(v, g_Bhi[n * CC + k], g_Blo[n * CC + k]);
}
__global__ void splitW_N_kernel(const float* __restrict__ W) {
    int n = blockIdx.x, k = threadIdx.x;
    float v = W[n * CC + k];
    split1(v, g_Bhi[n * CC + k], g_Blo[n * CC + k]);
}

// ---------------- bf16-split tensor-core GEMM (ldmatrix fragments) --------
#define SPAD 40            // smem row stride in bf16 elems (32 + 8 pad)
#define STAGE_E (128*SPAD)

__global__ __launch_bounds__(256, 2)
void gemm_bf16split(const __nv_bfloat16* __restrict__ Ah,
                    const __nv_bfloat16* __restrict__ Al,
                    const __nv_bfloat16* __restrict__ Bh,
                    const __nv_bfloat16* __restrict__ Bl,
                    float* __restrict__ C,
                    const float* __restrict__ bias,
                    int M, int relu) {
    extern __shared__ __nv_bfloat16 sm[];
    __nv_bfloat16* sAh = sm;
    __nv_bfloat16* sAl = sm + 2 * STAGE_E;
    __nv_bfloat16* sBh = sm + 4 * STAGE_E;
    __nv_bfloat16* sBl = sm + 6 * STAGE_E;

    const int tid = threadIdx.x;
    const int lane = tid & 31;
    const int wid = tid >> 5;
    const int warpM = wid & 1;
    const int warpN = wid >> 1;
    const int g = lane >> 2;
    const int t = lane & 3;
    const int M0 = blockIdx.y * 128;
    const int colBase = blockIdx.x * 128;

    const int row0 = tid >> 2;
    const int cc0  = tid & 3;
    const int row1 = (tid + 256) >> 2;

    const int a_row_l = warpM * 64 + (lane & 15);
    const int a_col_l = (lane >> 4) * 8;
    const int b_row_l = warpN * 32 + ((lane >> 4) & 1) * 8 + (lane & 7);
    const int b_col_l = ((lane >> 3) & 1) * 8;

    float acc[4][4][4];
#pragma unroll
    for (int i = 0; i < 4; i++)
#pragma unroll
        for (int j = 0; j < 4; j++)
#pragma unroll
            for (int k = 0; k < 4; k++) acc[i][j][k] = 0.f;

    auto loadTiles = [&](int stage, int kt) {
        __nv_bfloat16* dAh = sAh + stage * STAGE_E;
        __nv_bfloat16* dAl = sAl + stage * STAGE_E;
        __nv_bfloat16* dBh = sBh + stage * STAGE_E;
        __nv_bfloat16* dBl = sBl + stage * STAGE_E;
        {
            int gr = M0 + row0;
            int sz = (gr < M) ? 16 : 0;
            int gro = (gr < M) ? gr : 0;
            size_t go = (size_t)gro * CC + kt + cc0 * 8;
            cpasync16(dAh + row0 * SPAD + cc0 * 8, Ah + go, sz);
            cpasync16(dAl + row0 * SPAD + cc0 * 8, Al + go, sz);
        }
        {
            int gr = M0 + row1;
            int sz = (gr < M) ? 16 : 0;
            int gro = (gr < M) ? gr : 0;
            size_t go = (size_t)gro * CC + kt + cc0 * 8;
            cpasync16(dAh + row1 * SPAD + cc0 * 8, Ah + go, sz);
            cpasync16(dAl + row1 * SPAD + cc0 * 8, Al + go, sz);
        }
        {
            size_t go = (size_t)(colBase + row0) * CC + kt + cc0 * 8;
            cpasync16(dBh + row0 * SPAD + cc0 * 8, Bh + go, 16);
            cpasync16(dBl + row0 * SPAD + cc0 * 8, Bl + go, 16);
            size_t go1 = (size_t)(colBase + row1) * CC + kt + cc0 * 8;
            cpasync16(dBh + row1 * SPAD + cc0 * 8, Bh + go1, 16);
            cpasync16(dBl + row1 * SPAD + cc0 * 8, Bl + go1, 16);
        }
    };

    loadTiles(0, 0);
    asm volatile("cp.async.commit_group;");

    for (int kt = 0; kt < 8; kt++) {
        if (kt < 7) {
            loadTiles((kt + 1) & 1, (kt + 1) * 32);
            asm volatile("cp.async.commit_group;");
            asm volatile("cp.async.wait_group 1;");
        } else {
            asm volatile("cp.async.wait_group 0;");
        }
        __syncthreads();

        int stage = kt & 1;
        const uint32_t uAh = smem_u32(sAh + stage * STAGE_E);
        const uint32_t uAl = smem_u32(sAl + stage * STAGE_E);
        const uint32_t uBh = smem_u32(sBh + stage * STAGE_E);
        const uint32_t uBl = smem_u32(sBl + stage * STAGE_E);

#pragma unroll
        for (int ks = 0; ks < 32; ks += 16) {
            uint32_t af[4][4], bhf[4][2], blf[4][2];
            const uint32_t aoff = (uint32_t)((a_row_l * SPAD + ks + a_col_l) * 2);
            const uint32_t boff = (uint32_t)((b_row_l * SPAD + ks + b_col_l) * 2);
#pragma unroll
            for (int mt = 0; mt < 4; mt++)
                LDMX4(af[mt][0], af[mt][1], af[mt][2], af[mt][3],
                      uAh + aoff + mt * (16 * SPAD * 2));
#pragma unroll
            for (int np = 0; np < 2; np++) {
                LDMX4(bhf[2*np][0], bhf[2*np][1], bhf[2*np+1][0], bhf[2*np+1][1],
                      uBh + boff + np * (16 * SPAD * 2));
                LDMX4(blf[2*np][0], blf[2*np][1], blf[2*np+1][0], blf[2*np+1][1],
                      uBl + boff + np * (16 * SPAD * 2));
            }
#pragma unroll
            for (int mt = 0; mt < 4; mt++)
#pragma unroll
                for (int nt = 0; nt < 4; nt++)
                    MMA_BF16(acc[mt][nt], af[mt], bhf[nt]);
#pragma unroll
            for (int mt = 0; mt < 4; mt++)
#pragma unroll
                for (int nt = 0; nt < 4; nt++)
                    MMA_BF16(acc[mt][nt], af[mt], blf[nt]);
#pragma unroll
            for (int mt = 0; mt < 4; mt++)
                LDMX4(af[mt][0], af[mt][1], af[mt][2], af[mt][3],
                      uAl + aoff + mt * (16 * SPAD * 2));
#pragma unroll
            for (int mt = 0; mt < 4; mt++)
#pragma unroll
                for (int nt = 0; nt < 4; nt++)
                    MMA_BF16(acc[mt][nt], af[mt], bhf[nt]);
        }
        __syncthreads();
    }

#pragma unroll
    for (int mt = 0; mt < 4; mt++) {
        int r0 = M0 + warpM * 64 + mt * 16 + g;
#pragma unroll
        for (int nt = 0; nt < 4; nt++) {
            int c0 = colBase + warpN * 32 + nt * 8 + 2 * t;
            float2 v01 = make_float2(acc[mt][nt][0], acc[mt][nt][1]);
            float2 v23 = make_float2(acc[mt][nt][2], acc[mt][nt][3]);
            if (bias) {
                float b0 = bias[c0], b1 = bias[c0 + 1];
                v01.x += b0; v01.y += b1;
                v23.x += b0; v23.y += b1;
            }
            if (relu) {
                v01.x = fmaxf(v01.x, 0.f); v01.y = fmaxf(v01.y, 0.f);
                v23.x = fmaxf(v23.x, 0.f); v23.y = fmaxf(v23.y, 0.f);
            }
            if (r0 < M)     *(float2*)(C + (size_t)r0 * CC + c0) = v01;
            if (r0 + 8 < M) *(float2*)(C + (size_t)(r0 + 8) * CC + c0) = v23;
        }
    }
}

// ---------------- CSR aggregation: warp per destination node --------------
// out[d] = sum_e ex_e * h[src_e] / sum_e ex_e, ex = exp(leaky(as[s]+ad[d]))
__global__ __launch_bounds__(256)
void csr_aggr_kernel(const float* __restrict__ h, float* __restrict__ out) {
    int d = (blockIdx.x * blockDim.x + threadIdx.x) >> 5;
    int lane = threadIdx.x & 31;
    if (d >= NN) return;
    int start = g_rowstart[d];
    int end   = g_rowstart[d + 1];
    float add = g_ad[d];
    float4 a0 = make_float4(0.f, 0.f, 0.f, 0.f);
    float4 a1 = a0;
    float den = 0.f;
    for (int j = start; j < end; j++) {
        int s = __ldg(&g_csr_src[j]);
        float e = g_as[s] + add;
        e = (e > 0.f) ? e : 0.2f * e;
        float ex = expf(e);
        const float4* hp = (const float4*)(h + (size_t)s * CC);
        float4 v0 = __ldg(hp + lane);
        float4 v1 = __ldg(hp + lane + 32);
        a0.x = fmaf(ex, v0.x, a0.x); a0.y = fmaf(ex, v0.y, a0.y);
        a0.z = fmaf(ex, v0.z, a0.z); a0.w = fmaf(ex, v0.w, a0.w);
        a1.x = fmaf(ex, v1.x, a1.x); a1.y = fmaf(ex, v1.y, a1.y);
        a1.z = fmaf(ex, v1.z, a1.z); a1.w = fmaf(ex, v1.w, a1.w);
        den += ex;
    }
    float inv = 1.f / den;
    a0.x *= inv; a0.y *= inv; a0.z *= inv; a0.w *= inv;
    a1.x *= inv; a1.y *= inv; a1.z *= inv; a1.w *= inv;
    float4* op = (float4*)(out + (size_t)d * CC);
    op[lane]      = a0;
    op[lane + 32] = a1;
}

// ---------------- launch ----------------
extern "C" void kernel_launch(void* const* d_in, const int* in_sizes, int n_in,
                              void* d_out, int out_size) {
    const float* x    = (const float*)d_in[0];
    const int*   ei   = (const int*)d_in[1];
    const float* W1   = (const float*)d_in[2];
    const float* a1s  = (const float*)d_in[3];
    const float* a1d  = (const float*)d_in[4];
    const float* b1   = (const float*)d_in[5];
    const float* W2   = (const float*)d_in[6];
    const float* a2s  = (const float*)d_in[7];
    const float* a2d  = (const float*)d_in[8];
    const float* b2   = (const float*)d_in[9];
    const float* Wl   = (const float*)d_in[10];
    const float* bl   = (const float*)d_in[11];
    float* out = (float*)d_out;

    const int* src = ei;
    const int* dst = ei + EE;

    float *ph, *pacc;
    __nv_bfloat16 *pAh, *pAl, *pBh, *pBl;
    cudaGetSymbolAddress((void**)&ph,   g_h);
    cudaGetSymbolAddress((void**)&pacc, g_acc);
    cudaGetSymbolAddress((void**)&pAh,  g_Ahi);
    cudaGetSymbolAddress((void**)&pAl,  g_Alo);
    cudaGetSymbolAddress((void**)&pBh,  g_Bhi);
    cudaGetSymbolAddress((void**)&pBl,  g_Blo);

    static const int SMEM_BYTES = 8 * STAGE_E * 2;  // 81920
    cudaFuncSetAttribute(gemm_bf16split,
                         cudaFuncAttributeMaxDynamicSharedMemorySize, SMEM_BYTES);

    dim3 gemmGrid(2, (NN + 127) / 128);
    int rowBlocks = (NN + 7) / 8;         // warp-per-row / warp-per-node
    int eeBlocks  = (EE + 255) / 256;
    int etBlocks  = (ET + 255) / 256;
    int nnBlocks  = (NN + 255) / 256;

    // ---- CSR build (edges identical for both layers) ----
    csr_deg_init_kernel<<<nnBlocks, 256>>>();
    csr_count_kernel<<<eeBlocks, 256>>>(dst);
    scan1_kernel<<<SCAN_G, SCAN_B>>>();
    scan2_kernel<<<1, SCAN_B>>>();
    scan3_kernel<<<SCAN_G, SCAN_B>>>();
    csr_scatter_kernel<<<etBlocks, 256>>>(src, dst);

    // ---- layer 1 ----
    wsd_kernel<<<32, 256>>>(W1, a1s, a1d);
    split_x_alpha_kernel<<<rowBlocks, 256>>>(x);
    splitW_T_kernel<<<CC, CC>>>(W1);
    gemm_bf16split<<<gemmGrid, 256, SMEM_BYTES>>>(pAh, pAl, pBh, pBl, ph, nullptr, NN, 0);
    csr_aggr_kernel<<<rowBlocks, 256>>>(ph, pacc);

    // ---- layer 2 ----
    wsd_kernel<<<32, 256>>>(W2, a2s, a2d);
    bias_relu_alpha_split_kernel<<<rowBlocks, 256>>>(pacc, b1, 1);
    splitW_T_kernel<<<CC, CC>>>(W2);
    gemm_bf16split<<<gemmGrid, 256, SMEM_BYTES>>>(pAh, pAl, pBh, pBl, ph, nullptr, NN, 0);
    csr_aggr_kernel<<<rowBlocks, 256>>>(ph, pacc);

    // ---- final linear ----
    bias_relu_alpha_split_kernel<<<rowBlocks, 256>>>(pacc, b2, 0);
    splitW_N_kernel<<<CC, CC>>>(Wl);
    gemm_bf16split<<<gemmGrid, 256, SMEM_BYTES>>>(pAh, pAl, pBh, pBl, out, bl, NN, 0);
}

// round 8
// speedup vs baseline: 3.0688x; 1.4105x over previous
#include <cuda_runtime.h>
#include <cuda_fp16.h>
#include <cstdint>
#include <math.h>

#define NN 50000
#define EE 300000
#define ET (EE + NN)
#define CC 256

// ---------------- scratch (device globals) ----------------
__device__ float g_h[NN * CC];
__device__ __half g_A[NN * CC];        // GEMM A operand (fp16)
__device__ __half g_Bhi[CC * CC];      // [N][K] fp16 hi
__device__ __half g_Blo[CC * CC];      // [N][K] fp16 lo
__device__ float g_as[NN], g_ad[NN];
__device__ float g_as2[NN], g_ad2[NN];
__device__ float g_ws[CC], g_wd[CC];
// CSR
__device__ int g_deg[NN];
__device__ int g_rowstart[NN + 1];
__device__ int g_cursor[NN];
__device__ int g_csr_src[ET];
__device__ int g_bsum[256];

// ---------------- helpers ----------------
__device__ __forceinline__ void cpasync16(void* dst_smem, const void* src, int srcsize) {
    uint32_t d = (uint32_t)__cvta_generic_to_shared(dst_smem);
    asm volatile("cp.async.cg.shared.global [%0], [%1], 16, %2;"
                 :: "r"(d), "l"(src), "r"(srcsize));
}

__device__ __forceinline__ uint32_t smem_u32(const void* p) {
    return (uint32_t)__cvta_generic_to_shared(p);
}

#define MMA_F16(d, a, b) \
    asm volatile("mma.sync.aligned.m16n8k16.row.col.f32.f16.f16.f32 " \
                 "{%0,%1,%2,%3}, {%4,%5,%6,%7}, {%8,%9}, {%0,%1,%2,%3};" \
                 : "+f"(d[0]), "+f"(d[1]), "+f"(d[2]), "+f"(d[3]) \
                 : "r"(a[0]), "r"(a[1]), "r"(a[2]), "r"(a[3]), "r"(b[0]), "r"(b[1]))

#define LDMX4(r0, r1, r2, r3, addr) \
    asm volatile("ldmatrix.sync.aligned.m8n8.x4.shared.b16 {%0,%1,%2,%3}, [%4];" \
                 : "=r"(r0), "=r"(r1), "=r"(r2), "=r"(r3) : "r"(addr))

// =================== CSR build (once per launch) ===================
#define SCAN_B 256
#define SCAN_G ((NN + SCAN_B - 1) / SCAN_B)   // 196

__global__ void csr_deg_init_kernel() {
    int i = blockIdx.x * blockDim.x + threadIdx.x;
    if (i < NN) g_deg[i] = 1;   // self loop
}

__global__ void csr_count_kernel(const int* __restrict__ dst) {
    int i = blockIdx.x * blockDim.x + threadIdx.x;
    if (i < EE) atomicAdd(&g_deg[dst[i]], 1);
}

__global__ void scan1_kernel() {
    __shared__ int sd[SCAN_B];
    int t = threadIdx.x, i = blockIdx.x * SCAN_B + t;
    int v = (i < NN) ? g_deg[i] : 0;
    sd[t] = v;
    __syncthreads();
#pragma unroll
    for (int off = 1; off < SCAN_B; off <<= 1) {
        int x = (t >= off) ? sd[t - off] : 0;
        __syncthreads();
        sd[t] += x;
        __syncthreads();
    }
    if (i < NN) g_rowstart[i] = sd[t] - v;
    if (t == SCAN_B - 1) g_bsum[blockIdx.x] = sd[t];
}

__global__ void scan2_kernel() {
    __shared__ int sd[SCAN_B];
    int t = threadIdx.x;
    int v = (t < SCAN_G) ? g_bsum[t] : 0;
    sd[t] = v;
    __syncthreads();
#pragma unroll
    for (int off = 1; off < SCAN_B; off <<= 1) {
        int x = (t >= off) ? sd[t - off] : 0;
        __syncthreads();
        sd[t] += x;
        __syncthreads();
    }
    if (t < SCAN_G) g_bsum[t] = sd[t] - v;
}

__global__ void scan3_kernel() {
    int t = threadIdx.x, i = blockIdx.x * SCAN_B + t;
    if (i < NN) {
        int r = g_rowstart[i] + g_bsum[blockIdx.x];
        g_rowstart[i] = r;
        g_cursor[i] = r;
    }
    if (i == 0) g_rowstart[NN] = ET;
}

__global__ void csr_scatter_kernel(const int* __restrict__ src,
                                   const int* __restrict__ dst) {
    int i = blockIdx.x * blockDim.x + threadIdx.x;
    if (i >= ET) return;
    int s, d;
    if (i < EE) { s = src[i]; d = dst[i]; }
    else        { s = d = i - EE; }
    int pos = atomicAdd(&g_cursor[d], 1);
    g_csr_src[pos] = s;
}

// ---------------- ws = W @ a_src, wd = W @ a_dst ----------------
__global__ void wsd_kernel(const float* __restrict__ W,
                           const float* __restrict__ a_s,
                           const float* __restrict__ a_d) {
    int warp = (blockIdx.x * blockDim.x + threadIdx.x) >> 5;
    int lane = threadIdx.x & 31;
    if (warp >= CC) return;
    const float* row = W + (size_t)warp * CC;
    float s = 0.f, d = 0.f;
#pragma unroll
    for (int k = 0; k < 8; k++) {
        float v = row[lane + 32 * k];
        s = fmaf(v, a_s[lane + 32 * k], s);
        d = fmaf(v, a_d[lane + 32 * k], d);
    }
#pragma unroll
    for (int off = 16; off > 0; off >>= 1) {
        s += __shfl_xor_sync(0xffffffff, s, off);
        d += __shfl_xor_sync(0xffffffff, d, off);
    }
    if (lane == 0) { g_ws[warp] = s; g_wd[warp] = d; }
}

// ---------------- warp-per-row: x -> fp16 A + alphas ---------
__global__ __launch_bounds__(256)
void split_x_alpha_kernel(const float* __restrict__ X) {
    int warp = (blockIdx.x * blockDim.x + threadIdx.x) >> 5;
    int lane = threadIdx.x & 31;
    if (warp >= NN) return;
    const float4* xr = (const float4*)(X + (size_t)warp * CC);
    const float4* ws4 = (const float4*)g_ws;
    const float4* wd4 = (const float4*)g_wd;
    __half2* Ar = (__half2*)(g_A + (size_t)warp * CC);
    float s = 0.f, d = 0.f;
#pragma unroll
    for (int i = 0; i < 2; i++) {
        int idx = lane + 32 * i;
        float4 v = xr[idx];
        float4 a = ws4[idx];
        float4 b = wd4[idx];
        s += v.x*a.x + v.y*a.y + v.z*a.z + v.w*a.w;
        d += v.x*b.x + v.y*b.y + v.z*b.z + v.w*b.w;
        Ar[2*idx]   = __floats2half2_rn(v.x, v.y);
        Ar[2*idx+1] = __floats2half2_rn(v.z, v.w);
    }
#pragma unroll
    for (int off = 16; off > 0; off >>= 1) {
        s += __shfl_xor_sync(0xffffffff, s, off);
        d += __shfl_xor_sync(0xffffffff, d, off);
    }
    if (lane == 0) { g_as[warp] = s; g_ad[warp] = d; }
}

// weight split: W [K,N] -> [N,K] fp16 hi/lo (transpose), or Wl [N,K] direct
__global__ void splitW_T_kernel(const float* __restrict__ W) {
    int n = blockIdx.x, k = threadIdx.x;
    float v = W[k * CC + n];
    __half h = __float2half_rn(v);
    g_Bhi[n * CC + k] = h;
    g_Blo[n * CC + k] = __float2half_rn(v - __half2float(h));
}
__global__ void splitW_N_kernel(const float* __restrict__ W) {
    int n = blockIdx.x, k = threadIdx.x;
    float v = W[n * CC + k];
    __half h = __float2half_rn(v);
    g_Bhi[n * CC + k] = h;
    g_Blo[n * CC + k] = __float2half_rn(v - __half2float(h));
}

// ---------------- fp16 2-pass tensor-core GEMM ----------------
// C[M,256] = A @ (Bhi + Blo)^T   (B stored [N,K]; A fp16 single)
// 128x128 CTA tile, 8 warps (2M x 4N), warp tile 64x32, BK=32, 2-stage cp.async.
#define SPAD 40            // smem row stride in fp16 elems (32 + 8 pad)
#define STAGE_E (128*SPAD)

__global__ __launch_bounds__(256, 2)
void gemm_f16(const __half* __restrict__ A,
              const __half* __restrict__ Bh,
              const __half* __restrict__ Bl,
              float* __restrict__ C,
              const float* __restrict__ bias,
              int M) {
    extern __shared__ __half sm[];
    __half* sA  = sm;
    __half* sBh = sm + 2 * STAGE_E;
    __half* sBl = sm + 4 * STAGE_E;

    const int tid = threadIdx.x;
    const int lane = tid & 31;
    const int wid = tid >> 5;
    const int warpM = wid & 1;
    const int warpN = wid >> 1;
    const int g = lane >> 2;
    const int t = lane & 3;
    const int M0 = blockIdx.y * 128;
    const int colBase = blockIdx.x * 128;

    const int row0 = tid >> 2;
    const int cc0  = tid & 3;
    const int row1 = (tid + 256) >> 2;

    const int a_row_l = warpM * 64 + (lane & 15);
    const int a_col_l = (lane >> 4) * 8;
    const int b_row_l = warpN * 32 + ((lane >> 4) & 1) * 8 + (lane & 7);
    const int b_col_l = ((lane >> 3) & 1) * 8;

    float acc[4][4][4];
#pragma unroll
    for (int i = 0; i < 4; i++)
#pragma unroll
        for (int j = 0; j < 4; j++)
#pragma unroll
            for (int k = 0; k < 4; k++) acc[i][j][k] = 0.f;

    auto loadTiles = [&](int stage, int kt) {
        __half* dA  = sA  + stage * STAGE_E;
        __half* dBh = sBh + stage * STAGE_E;
        __half* dBl = sBl + stage * STAGE_E;
        {
            int gr = M0 + row0;
            int sz = (gr < M) ? 16 : 0;
            int gro = (gr < M) ? gr : 0;
            cpasync16(dA + row0 * SPAD + cc0 * 8, A + (size_t)gro * CC + kt + cc0 * 8, sz);
        }
        {
            int gr = M0 + row1;
            int sz = (gr < M) ? 16 : 0;
            int gro = (gr < M) ? gr : 0;
            cpasync16(dA + row1 * SPAD + cc0 * 8, A + (size_t)gro * CC + kt + cc0 * 8, sz);
        }
        {
            size_t go0 = (size_t)(colBase + row0) * CC + kt + cc0 * 8;
            size_t go1 = (size_t)(colBase + row1) * CC + kt + cc0 * 8;
            cpasync16(dBh + row0 * SPAD + cc0 * 8, Bh + go0, 16);
            cpasync16(dBl + row0 * SPAD + cc0 * 8, Bl + go0, 16);
            cpasync16(dBh + row1 * SPAD + cc0 * 8, Bh + go1, 16);
            cpasync16(dBl + row1 * SPAD + cc0 * 8, Bl + go1, 16);
        }
    };

    loadTiles(0, 0);
    asm volatile("cp.async.commit_group;");

    for (int kt = 0; kt < 8; kt++) {
        if (kt < 7) {
            loadTiles((kt + 1) & 1, (kt + 1) * 32);
            asm volatile("cp.async.commit_group;");
            asm volatile("cp.async.wait_group 1;");
        } else {
            asm volatile("cp.async.wait_group 0;");
        }
        __syncthreads();

        int stage = kt & 1;
        const uint32_t uA  = smem_u32(sA  + stage * STAGE_E);
        const uint32_t uBh = smem_u32(sBh + stage * STAGE_E);
        const uint32_t uBl = smem_u32(sBl + stage * STAGE_E);

#pragma unroll
        for (int ks = 0; ks < 32; ks += 16) {
            uint32_t af[4][4], bhf[4][2], blf[4][2];
            const uint32_t aoff = (uint32_t)((a_row_l * SPAD + ks + a_col_l) * 2);
            const uint32_t boff = (uint32_t)((b_row_l * SPAD + ks + b_col_l) * 2);
#pragma unroll
            for (int mt = 0; mt < 4; mt++)
                LDMX4(af[mt][0], af[mt][1], af[mt][2], af[mt][3],
                      uA + aoff + mt * (16 * SPAD * 2));
#pragma unroll
            for (int np = 0; np < 2; np++) {
                LDMX4(bhf[2*np][0], bhf[2*np][1], bhf[2*np+1][0], bhf[2*np+1][1],
                      uBh + boff + np * (16 * SPAD * 2));
                LDMX4(blf[2*np][0], blf[2*np][1], blf[2*np+1][0], blf[2*np+1][1],
                      uBl + boff + np * (16 * SPAD * 2));
            }
            // pass 1: A * Bhi
#pragma unroll
            for (int mt = 0; mt < 4; mt++)
#pragma unroll
                for (int nt = 0; nt < 4; nt++)
                    MMA_F16(acc[mt][nt], af[mt], bhf[nt]);
            // pass 2: A * Blo
#pragma unroll
            for (int mt = 0; mt < 4; mt++)
#pragma unroll
                for (int nt = 0; nt < 4; nt++)
                    MMA_F16(acc[mt][nt], af[mt], blf[nt]);
        }
        __syncthreads();
    }

#pragma unroll
    for (int mt = 0; mt < 4; mt++) {
        int r0 = M0 + warpM * 64 + mt * 16 + g;
#pragma unroll
        for (int nt = 0; nt < 4; nt++) {
            int c0 = colBase + warpN * 32 + nt * 8 + 2 * t;
            float2 v01 = make_float2(acc[mt][nt][0], acc[mt][nt][1]);
            float2 v23 = make_float2(acc[mt][nt][2], acc[mt][nt][3]);
            if (bias) {
                float b0 = bias[c0], b1 = bias[c0 + 1];
                v01.x += b0; v01.y += b1;
                v23.x += b0; v23.y += b1;
            }
            if (r0 < M)     *(float2*)(C + (size_t)r0 * CC + c0) = v01;
            if (r0 + 8 < M) *(float2*)(C + (size_t)(r0 + 8) * CC + c0) = v23;
        }
    }
}

// ---------------- CSR aggregation + fused bias/relu/alpha/fp16-split ------
// out_row = (sum_e ex_e*h[src_e]) / (sum_e ex_e); v = relu(out_row + bias)
// writes g_A fp16; optionally alphas for next layer into as_out/ad_out.
__global__ __launch_bounds__(256)
void csr_aggr_kernel(const float* __restrict__ h,
                     const float* __restrict__ bias,
                     const float* __restrict__ as_in,
                     const float* __restrict__ ad_in,
                     float* __restrict__ as_out,
                     float* __restrict__ ad_out,
                     int do_alpha) {
    int d = (blockIdx.x * blockDim.x + threadIdx.x) >> 5;
    int lane = threadIdx.x & 31;
    if (d >= NN) return;
    int start = g_rowstart[d];
    int end   = g_rowstart[d + 1];
    float add = ad_in[d];
    float4 a0 = make_float4(0.f, 0.f, 0.f, 0.f);
    float4 a1 = a0;
    float den = 0.f;
    for (int j = start; j < end; j++) {
        int s = __ldg(&g_csr_src[j]);
        float e = as_in[s] + add;
        e = (e > 0.f) ? e : 0.2f * e;
        float ex = expf(e);
        const float4* hp = (const float4*)(h + (size_t)s * CC);
        float4 v0 = __ldg(hp + lane);
        float4 v1 = __ldg(hp + lane + 32);
        a0.x = fmaf(ex, v0.x, a0.x); a0.y = fmaf(ex, v0.y, a0.y);
        a0.z = fmaf(ex, v0.z, a0.z); a0.w = fmaf(ex, v0.w, a0.w);
        a1.x = fmaf(ex, v1.x, a1.x); a1.y = fmaf(ex, v1.y, a1.y);
        a1.z = fmaf(ex, v1.z, a1.z); a1.w = fmaf(ex, v1.w, a1.w);
        den += ex;
    }
    float inv = 1.f / den;
    const float4* bias4 = (const float4*)bias;
    float4 bb0 = bias4[lane], bb1 = bias4[lane + 32];
    a0.x = fmaxf(fmaf(a0.x, inv, bb0.x), 0.f);
    a0.y = fmaxf(fmaf(a0.y, inv, bb0.y), 0.f);
    a0.z = fmaxf(fmaf(a0.z, inv, bb0.z), 0.f);
    a0.w = fmaxf(fmaf(a0.w, inv, bb0.w), 0.f);
    a1.x = fmaxf(fmaf(a1.x, inv, bb1.x), 0.f);
    a1.y = fmaxf(fmaf(a1.y, inv, bb1.y), 0.f);
    a1.z = fmaxf(fmaf(a1.z, inv, bb1.z), 0.f);
    a1.w = fmaxf(fmaf(a1.w, inv, bb1.w), 0.f);

    __half2* Ar = (__half2*)(g_A + (size_t)d * CC);
    Ar[2*lane]          = __floats2half2_rn(a0.x, a0.y);
    Ar[2*lane + 1]      = __floats2half2_rn(a0.z, a0.w);
    Ar[2*(lane+32)]     = __floats2half2_rn(a1.x, a1.y);
    Ar[2*(lane+32) + 1] = __floats2half2_rn(a1.z, a1.w);

    if (do_alpha) {
        const float4* ws4 = (const float4*)g_ws;
        const float4* wd4 = (const float4*)g_wd;
        float4 w0 = ws4[lane], w1 = ws4[lane + 32];
        float4 u0 = wd4[lane], u1 = wd4[lane + 32];
        float s = a0.x*w0.x + a0.y*w0.y + a0.z*w0.z + a0.w*w0.w
                + a1.x*w1.x + a1.y*w1.y + a1.z*w1.z + a1.w*w1.w;
        float dd = a0.x*u0.x + a0.y*u0.y + a0.z*u0.z + a0.w*u0.w
                 + a1.x*u1.x + a1.y*u1.y + a1.z*u1.z + a1.w*u1.w;
#pragma unroll
        for (int off = 16; off > 0; off >>= 1) {
            s  += __shfl_xor_sync(0xffffffff, s, off);
            dd += __shfl_xor_sync(0xffffffff, dd, off);
        }
        if (lane == 0) { as_out[d] = s; ad_out[d] = dd; }
    }
}

// ---------------- launch ----------------
extern "C" void kernel_launch(void* const* d_in, const int* in_sizes, int n_in,
                              void* d_out, int out_size) {
    const float* x    = (const float*)d_in[0];
    const int*   ei   = (const int*)d_in[1];
    const float* W1   = (const float*)d_in[2];
    const float* a1s  = (const float*)d_in[3];
    const float* a1d  = (const float*)d_in[4];
    const float* b1   = (const float*)d_in[5];
    const float* W2   = (const float*)d_in[6];
    const float* a2s  = (const float*)d_in[7];
    const float* a2d  = (const float*)d_in[8];
    const float* b2   = (const float*)d_in[9];
    const float* Wl   = (const float*)d_in[10];
    const float* bl   = (const float*)d_in[11];
    float* out = (float*)d_out;

    const int* src = ei;
    const int* dst = ei + EE;

    float *ph, *pas, *pad, *pas2, *pad2;
    __half *pA, *pBh, *pBl;
    cudaGetSymbolAddress((void**)&ph,   g_h);
    cudaGetSymbolAddress((void**)&pA,   g_A);
    cudaGetSymbolAddress((void**)&pBh,  g_Bhi);
    cudaGetSymbolAddress((void**)&pBl,  g_Blo);
    cudaGetSymbolAddress((void**)&pas,  g_as);
    cudaGetSymbolAddress((void**)&pad,  g_ad);
    cudaGetSymbolAddress((void**)&pas2, g_as2);
    cudaGetSymbolAddress((void**)&pad2, g_ad2);

    static const int SMEM_BYTES = 6 * STAGE_E * 2;  // 61440
    cudaFuncSetAttribute(gemm_f16,
                         cudaFuncAttributeMaxDynamicSharedMemorySize, SMEM_BYTES);

    dim3 gemmGrid(2, (NN + 127) / 128);
    int rowBlocks = (NN + 7) / 8;
    int eeBlocks  = (EE + 255) / 256;
    int etBlocks  = (ET + 255) / 256;
    int nnBlocks  = (NN + 255) / 256;

    // ---- CSR build (edges identical for both layers) ----
    csr_deg_init_kernel<<<nnBlocks, 256>>>();
    csr_count_kernel<<<eeBlocks, 256>>>(dst);
    scan1_kernel<<<SCAN_G, SCAN_B>>>();
    scan2_kernel<<<1, SCAN_B>>>();
    scan3_kernel<<<SCAN_G, SCAN_B>>>();
    csr_scatter_kernel<<<etBlocks, 256>>>(src, dst);

    // ---- layer 1 ----
    wsd_kernel<<<32, 256>>>(W1, a1s, a1d);
    split_x_alpha_kernel<<<rowBlocks, 256>>>(x);
    splitW_T_kernel<<<CC, CC>>>(W1);
    gemm_f16<<<gemmGrid, 256, SMEM_BYTES>>>(pA, pBh, pBl, ph, nullptr, NN);
    wsd_kernel<<<32, 256>>>(W2, a2s, a2d);   // ws/wd for layer-2 alphas
    csr_aggr_kernel<<<rowBlocks, 256>>>(ph, b1, pas, pad, pas2, pad2, 1);

    // ---- layer 2 ----
    splitW_T_kernel<<<CC, CC>>>(W2);
    gemm_f16<<<gemmGrid, 256, SMEM_BYTES>>>(pA, pBh, pBl, ph, nullptr, NN);
    csr_aggr_kernel<<<rowBlocks, 256>>>(ph, b2, pas2, pad2, nullptr, nullptr, 0);

    // ---- final linear ----
    splitW_N_kernel<<<CC, CC>>>(Wl);
    gemm_f16<<<gemmGrid, 256, SMEM_BYTES>>>(pA, pBh, pBl, out, bl, NN);
}

// round 9
// speedup vs baseline: 3.7855x; 1.2335x over previous
#include <cuda_runtime.h>
#include <cuda_fp16.h>
#include <cstdint>
#include <math.h>

#define NN 50000
#define EE 300000
#define ET (EE + NN)
#define CC 256

// ---------------- scratch (device globals) ----------------
__device__ float g_h[NN * CC];
__device__ __half g_A[NN * CC];        // GEMM A operand (fp16)
__device__ __half g_B[CC * CC];        // [N][K] fp16
__device__ float g_as[NN], g_ad[NN];
__device__ float g_as2[NN], g_ad2[NN];
__device__ float g_ws[CC], g_wd[CC];
// CSR
__device__ int g_deg[NN];
__device__ int g_rowstart[NN + 1];
__device__ int g_cursor[NN];
__device__ int g_csr_src[ET];
__device__ int g_bsum[256];

// ---------------- helpers ----------------
__device__ __forceinline__ void cpasync16(void* dst_smem, const void* src, int srcsize) {
    uint32_t d = (uint32_t)__cvta_generic_to_shared(dst_smem);
    asm volatile("cp.async.cg.shared.global [%0], [%1], 16, %2;"
                 :: "r"(d), "l"(src), "r"(srcsize));
}

__device__ __forceinline__ uint32_t smem_u32(const void* p) {
    return (uint32_t)__cvta_generic_to_shared(p);
}

#define MMA_F16(d, a, b) \
    asm volatile("mma.sync.aligned.m16n8k16.row.col.f32.f16.f16.f32 " \
                 "{%0,%1,%2,%3}, {%4,%5,%6,%7}, {%8,%9}, {%0,%1,%2,%3};" \
                 : "+f"(d[0]), "+f"(d[1]), "+f"(d[2]), "+f"(d[3]) \
                 : "r"(a[0]), "r"(a[1]), "r"(a[2]), "r"(a[3]), "r"(b[0]), "r"(b[1]))

#define LDMX4(r0, r1, r2, r3, addr) \
    asm volatile("ldmatrix.sync.aligned.m8n8.x4.shared.b16 {%0,%1,%2,%3}, [%4];" \
                 : "=r"(r0), "=r"(r1), "=r"(r2), "=r"(r3) : "r"(addr))

// =================== CSR build (once per launch) ===================
#define SCAN_B 256
#define SCAN_G ((NN + SCAN_B - 1) / SCAN_B)   // 196

__global__ void csr_deg_init_kernel() {
    int i = blockIdx.x * blockDim.x + threadIdx.x;
    if (i < NN) g_deg[i] = 1;   // self loop
}

__global__ void csr_count_kernel(const int* __restrict__ dst) {
    int i = blockIdx.x * blockDim.x + threadIdx.x;
    if (i < EE) atomicAdd(&g_deg[dst[i]], 1);
}

__global__ void scan1_kernel() {
    __shared__ int sd[SCAN_B];
    int t = threadIdx.x, i = blockIdx.x * SCAN_B + t;
    int v = (i < NN) ? g_deg[i] : 0;
    sd[t] = v;
    __syncthreads();
#pragma unroll
    for (int off = 1; off < SCAN_B; off <<= 1) {
        int x = (t >= off) ? sd[t - off] : 0;
        __syncthreads();
        sd[t] += x;
        __syncthreads();
    }
    if (i < NN) g_rowstart[i] = sd[t] - v;
    if (t == SCAN_B - 1) g_bsum[blockIdx.x] = sd[t];
}

__global__ void scan2_kernel() {
    __shared__ int sd[SCAN_B];
    int t = threadIdx.x;
    int v = (t < SCAN_G) ? g_bsum[t] : 0;
    sd[t] = v;
    __syncthreads();
#pragma unroll
    for (int off = 1; off < SCAN_B; off <<= 1) {
        int x = (t >= off) ? sd[t - off] : 0;
        __syncthreads();
        sd[t] += x;
        __syncthreads();
    }
    if (t < SCAN_G) g_bsum[t] = sd[t] - v;
}

__global__ void scan3_kernel() {
    int t = threadIdx.x, i = blockIdx.x * SCAN_B + t;
    if (i < NN) {
        int r = g_rowstart[i] + g_bsum[blockIdx.x];
        g_rowstart[i] = r;
        g_cursor[i] = r;
    }
    if (i == 0) g_rowstart[NN] = ET;
}

__global__ void csr_scatter_kernel(const int* __restrict__ src,
                                   const int* __restrict__ dst) {
    int i = blockIdx.x * blockDim.x + threadIdx.x;
    if (i >= ET) return;
    int s, d;
    if (i < EE) { s = src[i]; d = dst[i]; }
    else        { s = d = i - EE; }
    int pos = atomicAdd(&g_cursor[d], 1);
    g_csr_src[pos] = s;
}

// ---------------- ws = W @ a_src, wd = W @ a_dst ----------------
__global__ void wsd_kernel(const float* __restrict__ W,
                           const float* __restrict__ a_s,
                           const float* __restrict__ a_d) {
    int warp = (blockIdx.x * blockDim.x + threadIdx.x) >> 5;
    int lane = threadIdx.x & 31;
    if (warp >= CC) return;
    const float* row = W + (size_t)warp * CC;
    float s = 0.f, d = 0.f;
#pragma unroll
    for (int k = 0; k < 8; k++) {
        float v = row[lane + 32 * k];
        s = fmaf(v, a_s[lane + 32 * k], s);
        d = fmaf(v, a_d[lane + 32 * k], d);
    }
#pragma unroll
    for (int off = 16; off > 0; off >>= 1) {
        s += __shfl_xor_sync(0xffffffff, s, off);
        d += __shfl_xor_sync(0xffffffff, d, off);
    }
    if (lane == 0) { g_ws[warp] = s; g_wd[warp] = d; }
}

// ---------------- warp-per-row: x -> fp16 A + alphas ---------
__global__ __launch_bounds__(256)
void split_x_alpha_kernel(const float* __restrict__ X) {
    int warp = (blockIdx.x * blockDim.x + threadIdx.x) >> 5;
    int lane = threadIdx.x & 31;
    if (warp >= NN) return;
    const float4* xr = (const float4*)(X + (size_t)warp * CC);
    const float4* ws4 = (const float4*)g_ws;
    const float4* wd4 = (const float4*)g_wd;
    __half2* Ar = (__half2*)(g_A + (size_t)warp * CC);
    float s = 0.f, d = 0.f;
#pragma unroll
    for (int i = 0; i < 2; i++) {
        int idx = lane + 32 * i;
        float4 v = xr[idx];
        float4 a = ws4[idx];
        float4 b = wd4[idx];
        s += v.x*a.x + v.y*a.y + v.z*a.z + v.w*a.w;
        d += v.x*b.x + v.y*b.y + v.z*b.z + v.w*b.w;
        Ar[2*idx]   = __floats2half2_rn(v.x, v.y);
        Ar[2*idx+1] = __floats2half2_rn(v.z, v.w);
    }
#pragma unroll
    for (int off = 16; off > 0; off >>= 1) {
        s += __shfl_xor_sync(0xffffffff, s, off);
        d += __shfl_xor_sync(0xffffffff, d, off);
    }
    if (lane == 0) { g_as[warp] = s; g_ad[warp] = d; }
}

// weight convert: W [K,N] -> [N,K] fp16 (transpose), or Wl [N,K] direct
__global__ void convW_T_kernel(const float* __restrict__ W) {
    int n = blockIdx.x, k = threadIdx.x;
    g_B[n * CC + k] = __float2half_rn(W[k * CC + n]);
}
__global__ void convW_N_kernel(const float* __restrict__ W) {
    int n = blockIdx.x, k = threadIdx.x;
    g_B[n * CC + k] = __float2half_rn(W[n * CC + k]);
}

// ---------------- fp16 single-pass tensor-core GEMM ----------------
// C[M,256] = A @ B^T   (B stored [N,K]; both fp16, fp32 accum)
// 128x128 CTA tile, 8 warps (2M x 4N), warp tile 64x32, BK=32, 2-stage cp.async.
#define SPAD 40            // smem row stride in fp16 elems (32 + 8 pad)
#define STAGE_E (128*SPAD)

__global__ __launch_bounds__(256, 2)
void gemm_f16(const __half* __restrict__ A,
              const __half* __restrict__ B,
              float* __restrict__ C,
              const float* __restrict__ bias,
              int M) {
    extern __shared__ __half sm[];
    __half* sA = sm;
    __half* sB = sm + 2 * STAGE_E;

    const int tid = threadIdx.x;
    const int lane = tid & 31;
    const int wid = tid >> 5;
    const int warpM = wid & 1;
    const int warpN = wid >> 1;
    const int g = lane >> 2;
    const int t = lane & 3;
    const int M0 = blockIdx.y * 128;
    const int colBase = blockIdx.x * 128;

    const int row0 = tid >> 2;
    const int cc0  = tid & 3;
    const int row1 = (tid + 256) >> 2;

    const int a_row_l = warpM * 64 + (lane & 15);
    const int a_col_l = (lane >> 4) * 8;
    const int b_row_l = warpN * 32 + ((lane >> 4) & 1) * 8 + (lane & 7);
    const int b_col_l = ((lane >> 3) & 1) * 8;

    float acc[4][4][4];
#pragma unroll
    for (int i = 0; i < 4; i++)
#pragma unroll
        for (int j = 0; j < 4; j++)
#pragma unroll
            for (int k = 0; k < 4; k++) acc[i][j][k] = 0.f;

    auto loadTiles = [&](int stage, int kt) {
        __half* dA = sA + stage * STAGE_E;
        __half* dB = sB + stage * STAGE_E;
        {
            int gr = M0 + row0;
            int sz = (gr < M) ? 16 : 0;
            int gro = (gr < M) ? gr : 0;
            cpasync16(dA + row0 * SPAD + cc0 * 8, A + (size_t)gro * CC + kt + cc0 * 8, sz);
        }
        {
            int gr = M0 + row1;
            int sz = (gr < M) ? 16 : 0;
            int gro = (gr < M) ? gr : 0;
            cpasync16(dA + row1 * SPAD + cc0 * 8, A + (size_t)gro * CC + kt + cc0 * 8, sz);
        }
        {
            size_t go0 = (size_t)(colBase + row0) * CC + kt + cc0 * 8;
            size_t go1 = (size_t)(colBase + row1) * CC + kt + cc0 * 8;
            cpasync16(dB + row0 * SPAD + cc0 * 8, B + go0, 16);
            cpasync16(dB + row1 * SPAD + cc0 * 8, B + go1, 16);
        }
    };

    loadTiles(0, 0);
    asm volatile("cp.async.commit_group;");

    for (int kt = 0; kt < 8; kt++) {
        if (kt < 7) {
            loadTiles((kt + 1) & 1, (kt + 1) * 32);
            asm volatile("cp.async.commit_group;");
            asm volatile("cp.async.wait_group 1;");
        } else {
            asm volatile("cp.async.wait_group 0;");
        }
        __syncthreads();

        int stage = kt & 1;
        const uint32_t uA = smem_u32(sA + stage * STAGE_E);
        const uint32_t uB = smem_u32(sB + stage * STAGE_E);

#pragma unroll
        for (int ks = 0; ks < 32; ks += 16) {
            uint32_t af[4][4], bf[4][2];
            const uint32_t aoff = (uint32_t)((a_row_l * SPAD + ks + a_col_l) * 2);
            const uint32_t boff = (uint32_t)((b_row_l * SPAD + ks + b_col_l) * 2);
#pragma unroll
            for (int mt = 0; mt < 4; mt++)
                LDMX4(af[mt][0], af[mt][1], af[mt][2], af[mt][3],
                      uA + aoff + mt * (16 * SPAD * 2));
#pragma unroll
            for (int np = 0; np < 2; np++)
                LDMX4(bf[2*np][0], bf[2*np][1], bf[2*np+1][0], bf[2*np+1][1],
                      uB + boff + np * (16 * SPAD * 2));
#pragma unroll
            for (int mt = 0; mt < 4; mt++)
#pragma unroll
                for (int nt = 0; nt < 4; nt++)
                    MMA_F16(acc[mt][nt], af[mt], bf[nt]);
        }
        __syncthreads();
    }

#pragma unroll
    for (int mt = 0; mt < 4; mt++) {
        int r0 = M0 + warpM * 64 + mt * 16 + g;
#pragma unroll
        for (int nt = 0; nt < 4; nt++) {
            int c0 = colBase + warpN * 32 + nt * 8 + 2 * t;
            float2 v01 = make_float2(acc[mt][nt][0], acc[mt][nt][1]);
            float2 v23 = make_float2(acc[mt][nt][2], acc[mt][nt][3]);
            if (bias) {
                float b0 = bias[c0], b1 = bias[c0 + 1];
                v01.x += b0; v01.y += b1;
                v23.x += b0; v23.y += b1;
            }
            if (r0 < M)     *(float2*)(C + (size_t)r0 * CC + c0) = v01;
            if (r0 + 8 < M) *(float2*)(C + (size_t)(r0 + 8) * CC + c0) = v23;
        }
    }
}

// ---------------- CSR aggregation + fused bias/relu/alpha/fp16 ------
__global__ __launch_bounds__(256)
void csr_aggr_kernel(const float* __restrict__ h,
                     const float* __restrict__ bias,
                     const float* __restrict__ as_in,
                     const float* __restrict__ ad_in,
                     float* __restrict__ as_out,
                     float* __restrict__ ad_out,
                     int do_alpha) {
    int d = (blockIdx.x * blockDim.x + threadIdx.x) >> 5;
    int lane = threadIdx.x & 31;
    if (d >= NN) return;
    int start = g_rowstart[d];
    int end   = g_rowstart[d + 1];
    float add = ad_in[d];
    float4 a0 = make_float4(0.f, 0.f, 0.f, 0.f);
    float4 a1 = a0;
    float den = 0.f;
    for (int j = start; j < end; j++) {
        int s = __ldg(&g_csr_src[j]);
        float e = as_in[s] + add;
        e = (e > 0.f) ? e : 0.2f * e;
        float ex = expf(e);
        const float4* hp = (const float4*)(h + (size_t)s * CC);
        float4 v0 = __ldg(hp + lane);
        float4 v1 = __ldg(hp + lane + 32);
        a0.x = fmaf(ex, v0.x, a0.x); a0.y = fmaf(ex, v0.y, a0.y);
        a0.z = fmaf(ex, v0.z, a0.z); a0.w = fmaf(ex, v0.w, a0.w);
        a1.x = fmaf(ex, v1.x, a1.x); a1.y = fmaf(ex, v1.y, a1.y);
        a1.z = fmaf(ex, v1.z, a1.z); a1.w = fmaf(ex, v1.w, a1.w);
        den += ex;
    }
    float inv = 1.f / den;
    const float4* bias4 = (const float4*)bias;
    float4 bb0 = bias4[lane], bb1 = bias4[lane + 32];
    a0.x = fmaxf(fmaf(a0.x, inv, bb0.x), 0.f);
    a0.y = fmaxf(fmaf(a0.y, inv, bb0.y), 0.f);
    a0.z = fmaxf(fmaf(a0.z, inv, bb0.z), 0.f);
    a0.w = fmaxf(fmaf(a0.w, inv, bb0.w), 0.f);
    a1.x = fmaxf(fmaf(a1.x, inv, bb1.x), 0.f);
    a1.y = fmaxf(fmaf(a1.y, inv, bb1.y), 0.f);
    a1.z = fmaxf(fmaf(a1.z, inv, bb1.z), 0.f);
    a1.w = fmaxf(fmaf(a1.w, inv, bb1.w), 0.f);

    __half2* Ar = (__half2*)(g_A + (size_t)d * CC);
    Ar[2*lane]          = __floats2half2_rn(a0.x, a0.y);
    Ar[2*lane + 1]      = __floats2half2_rn(a0.z, a0.w);
    Ar[2*(lane+32)]     = __floats2half2_rn(a1.x, a1.y);
    Ar[2*(lane+32) + 1] = __floats2half2_rn(a1.z, a1.w);

    if (do_alpha) {
        const float4* ws4 = (const float4*)g_ws;
        const float4* wd4 = (const float4*)g_wd;
        float4 w0 = ws4[lane], w1 = ws4[lane + 32];
        float4 u0 = wd4[lane], u1 = wd4[lane + 32];
        float s = a0.x*w0.x + a0.y*w0.y + a0.z*w0.z + a0.w*w0.w
                + a1.x*w1.x + a1.y*w1.y + a1.z*w1.z + a1.w*w1.w;
        float dd = a0.x*u0.x + a0.y*u0.y + a0.z*u0.z + a0.w*u0.w
                 + a1.x*u1.x + a1.y*u1.y + a1.z*u1.z + a1.w*u1.w;
#pragma unroll
        for (int off = 16; off > 0; off >>= 1) {
            s  += __shfl_xor_sync(0xffffffff, s, off);
            dd += __shfl_xor_sync(0xffffffff, dd, off);
        }
        if (lane == 0) { as_out[d] = s; ad_out[d] = dd; }
    }
}

// ---------------- launch ----------------
extern "C" void kernel_launch(void* const* d_in, const int* in_sizes, int n_in,
                              void* d_out, int out_size) {
    const float* x    = (const float*)d_in[0];
    const int*   ei   = (const int*)d_in[1];
    const float* W1   = (const float*)d_in[2];
    const float* a1s  = (const float*)d_in[3];
    const float* a1d  = (const float*)d_in[4];
    const float* b1   = (const float*)d_in[5];
    const float* W2   = (const float*)d_in[6];
    const float* a2s  = (const float*)d_in[7];
    const float* a2d  = (const float*)d_in[8];
    const float* b2   = (const float*)d_in[9];
    const float* Wl   = (const float*)d_in[10];
    const float* bl   = (const float*)d_in[11];
    float* out = (float*)d_out;

    const int* src = ei;
    const int* dst = ei + EE;

    float *ph, *pas, *pad, *pas2, *pad2;
    __half *pA, *pB;
    cudaGetSymbolAddress((void**)&ph,   g_h);
    cudaGetSymbolAddress((void**)&pA,   g_A);
    cudaGetSymbolAddress((void**)&pB,   g_B);
    cudaGetSymbolAddress((void**)&pas,  g_as);
    cudaGetSymbolAddress((void**)&pad,  g_ad);
    cudaGetSymbolAddress((void**)&pas2, g_as2);
    cudaGetSymbolAddress((void**)&pad2, g_ad2);

    static const int SMEM_BYTES = 4 * STAGE_E * 2;  // 40960
    cudaFuncSetAttribute(gemm_f16,
                         cudaFuncAttributeMaxDynamicSharedMemorySize, SMEM_BYTES);

    dim3 gemmGrid(2, (NN + 127) / 128);
    int rowBlocks = (NN + 7) / 8;
    int eeBlocks  = (EE + 255) / 256;
    int etBlocks  = (ET + 255) / 256;
    int nnBlocks  = (NN + 255) / 256;

    // ---- CSR build (edges identical for both layers) ----
    csr_deg_init_kernel<<<nnBlocks, 256>>>();
    csr_count_kernel<<<eeBlocks, 256>>>(dst);
    scan1_kernel<<<SCAN_G, SCAN_B>>>();
    scan2_kernel<<<1, SCAN_B>>>();
    scan3_kernel<<<SCAN_G, SCAN_B>>>();
    csr_scatter_kernel<<<etBlocks, 256>>>(src, dst);

    // ---- layer 1 ----
    wsd_kernel<<<32, 256>>>(W1, a1s, a1d);
    split_x_alpha_kernel<<<rowBlocks, 256>>>(x);
    convW_T_kernel<<<CC, CC>>>(W1);
    gemm_f16<<<gemmGrid, 256, SMEM_BYTES>>>(pA, pB, ph, nullptr, NN);
    wsd_kernel<<<32, 256>>>(W2, a2s, a2d);   // ws/wd for layer-2 alphas
    csr_aggr_kernel<<<rowBlocks, 256>>>(ph, b1, pas, pad, pas2, pad2, 1);

    // ---- layer 2 ----
    convW_T_kernel<<<CC, CC>>>(W2);
    gemm_f16<<<gemmGrid, 256, SMEM_BYTES>>>(pA, pB, ph, nullptr, NN);
    csr_aggr_kernel<<<rowBlocks, 256>>>(ph, b2, pas2, pad2, nullptr, nullptr, 0);

    // ---- final linear ----
    convW_N_kernel<<<CC, CC>>>(Wl);
    gemm_f16<<<gemmGrid, 256, SMEM_BYTES>>>(pA, pB, out, bl, NN);
}